// round 13
// baseline (speedup 1.0000x reference)
#include <cuda_runtime.h>
#include <math.h>
#include <float.h>
#include <stdint.h>

#define BATCH 8
#define CDIM  256
#define HDIM  256
#define WDIM  32
#define SPA   8192      // HDIM*WDIM
#define FFI   1024
#define NBH   64        // BATCH*HEADS

// ------------------------- scratch (device globals) -------------------------
__device__ float g_xn  [BATCH*CDIM*SPA];
__device__ float g_xs  [BATCH*CDIM*SPA];
__device__ float g_qkv [BATCH*3*CDIM*SPA];
__device__ float g_or  [BATCH*CDIM*SPA];
__device__ float g_attn[BATCH*CDIM*SPA];
__device__ float g_conv[BATCH*CDIM*SPA];
__device__ float g_comb[BATCH*CDIM*SPA];
__device__ float g_ff1 [BATCH*FFI*SPA];
__device__ float g_ffdw[BATCH*FFI*SPA];
__device__ float g_ff2 [BATCH*CDIM*SPA];
__device__ float g_probe[NBH*32];
__device__ float g_k2 [NBH*64*32];
__device__ float g_v2 [NBH*64*32];
__device__ float g_wt [1310720];   // transposed (K-major), tf32-rounded weights

// wt offsets (floats)
#define WT_OUT  0          // 256 x 256
#define WT_COMB 65536      // 512 x 256
#define WT_FF1  196608     // 256 x 1024
#define WT_FF2  458752     // 1024 x 256
#define WT_QKV  720896     // 768 x 768  ([Wb; Ws; Wb] rows)

__device__ __forceinline__ uint32_t f2tf(float f) {
    uint32_t r;
    asm("cvt.rna.tf32.f32 %0, %1;" : "=r"(r) : "f"(f));
    return r;
}

// ------------------------- weight transpose (+ tf32 round) ------------------
__global__ void transpose_kernel(const float* __restrict__ w, float* __restrict__ wt,
                                 int M, int K) {
    __shared__ float t[32][33];
    int k0 = blockIdx.x*32, m0 = blockIdx.y*32;
    int tx = threadIdx.x & 31, ty = threadIdx.x >> 5;   // 32 x 8
    #pragma unroll
    for (int r = 0; r < 4; r++)
        t[ty + r*8][tx] = w[(size_t)(m0 + ty + r*8)*K + k0 + tx];
    __syncthreads();
    #pragma unroll
    for (int r = 0; r < 4; r++)
        wt[(size_t)(k0 + ty + r*8)*M + m0 + tx] =
            __uint_as_float(f2tf(t[tx][ty + r*8]));
}

// qkv weight: [768][256] -> wq [768 rows][768 cols]: rows 0-255 = Wb^T,
// 256-511 = Ws^T, 512-767 = Wb^T (for the K=768 split GEMM).
__global__ void transpose_split_qkv(const float* __restrict__ w, float* __restrict__ wq) {
    __shared__ float t[32][33];
    int k0 = blockIdx.x*32, m0 = blockIdx.y*32;   // k over 256, m over 768
    int tx = threadIdx.x & 31, ty = threadIdx.x >> 5;
    #pragma unroll
    for (int r = 0; r < 4; r++)
        t[ty + r*8][tx] = w[(size_t)(m0 + ty + r*8)*256 + k0 + tx];
    __syncthreads();
    #pragma unroll
    for (int r = 0; r < 4; r++) {
        int k = k0 + ty + r*8;
        int m = m0 + tx;
        float v = t[tx][ty + r*8];
        float big = __uint_as_float(f2tf(v));
        float sml = __uint_as_float(f2tf(v - big));
        wq[(size_t)k*768 + m]         = big;
        wq[(size_t)(256 + k)*768 + m] = sml;
        wq[(size_t)(512 + k)*768 + m] = big;
    }
}

// ------------------------- split X into tf32 big/small (in place) -----------
__global__ void split_x_kernel(float* __restrict__ xb, float* __restrict__ xs, int n4) {
    int i = blockIdx.x*blockDim.x + threadIdx.x;
    if (i >= n4) return;
    float4 v = ((float4*)xb)[i];
    float4 b, s;
    b.x = __uint_as_float(f2tf(v.x)); s.x = __uint_as_float(f2tf(v.x - b.x));
    b.y = __uint_as_float(f2tf(v.y)); s.y = __uint_as_float(f2tf(v.y - b.y));
    b.z = __uint_as_float(f2tf(v.z)); s.z = __uint_as_float(f2tf(v.z - b.z));
    b.w = __uint_as_float(f2tf(v.w)); s.w = __uint_as_float(f2tf(v.w - b.w));
    ((float4*)xb)[i] = b;
    ((float4*)xs)[i] = s;
}

// ------------------------- channel LayerNorm (axis=C) -----------------------
__global__ void chan_ln_kernel(const float* __restrict__ x,
                               const float* __restrict__ gma,
                               const float* __restrict__ bta,
                               float* __restrict__ xn) {
    __shared__ float  xsm[CDIM*32];
    __shared__ double ssum[8][32];
    __shared__ double ssq [8][32];
    __shared__ float  mbuf[32], rbuf[32];
    int b = blockIdx.y, hh = blockIdx.x;
    int tid = threadIdx.x;
    int cg = tid >> 5, p = tid & 31;
    const float* xb = x + (size_t)b*CDIM*SPA + hh*WDIM + p;
    double s = 0.0, s2 = 0.0;
    #pragma unroll
    for (int j = 0; j < 32; j++) {
        int c = cg*32 + j;
        float v = xb[(size_t)c*SPA];
        xsm[c*32 + p] = v;
        s += v; s2 += (double)v*(double)v;
    }
    ssum[cg][p] = s; ssq[cg][p] = s2;
    __syncthreads();
    if (tid < 32) {
        double ts = 0.0, tq = 0.0;
        #pragma unroll
        for (int g = 0; g < 8; g++) { ts += ssum[g][tid]; tq += ssq[g][tid]; }
        double m   = ts / 256.0;
        double var = tq / 256.0 - m*m;
        mbuf[tid] = (float)m;
        rbuf[tid] = (float)(1.0 / sqrt(var + 1e-5));
    }
    __syncthreads();
    float m = mbuf[p], r = rbuf[p];
    float* xo = xn + (size_t)b*CDIM*SPA + hh*WDIM + p;
    #pragma unroll
    for (int j = 0; j < 32; j++) {
        int c = cg*32 + j;
        xo[(size_t)c*SPA] = (xsm[c*32 + p] - m) * r * gma[c] + bta[c];
    }
}

// ------------------------- tf32 GEMM: 128x128x32, 4 warps, 64x64 warp tile --
// out[b,m,n] = bias[m] + sum_c wt[c][m] * X[b,c,n] (+res). X = concat(in1,in2)
// over logical channels [0,ic1log) -> in1 (row = wrap ? c&255 : c), rest -> in2.
// wt rows pre-rounded to tf32. cp.async double-buffered staging.
#define CP16(dst, src) asm volatile("cp.async.ca.shared.global [%0], [%1], 16;\n" \
    :: "r"(dst), "l"(src))

__global__ void __launch_bounds__(128)
gemm_tf32(const float* __restrict__ in1, const float* __restrict__ in2,
          int ic1log, int ic1p, int ic_total, int wrap,
          const float* __restrict__ wt, const float* __restrict__ bias,
          const float* __restrict__ res, float* __restrict__ out,
          int oc_total) {
    extern __shared__ float sm[];
    float* Wt0 = sm;              // [2][32*128]
    float* Xt0 = sm + 8192;       // [2][32*128]

    int oc0 = blockIdx.x * 128;
    int p0  = blockIdx.y * 128;
    int b   = blockIdx.z;
    int tid = threadIdx.x;
    int lane = tid & 31, wid = tid >> 5;
    int gid = lane >> 2, tig = lane & 3;
    int warpm0 = (wid & 1) * 64;
    int warpn0 = (wid >> 1) * 64;
    int swz = tig * 8;

    const float* in1b = in1 + (size_t)b*ic1p*SPA + p0;
    const float* in2b = in2 ? (in2 + (size_t)b*(ic_total - ic1log)*SPA + p0)
                            : (const float*)0;
    const float* wbase = wt + oc0 + lane*4;

    float acc[4][8][4];
    #pragma unroll
    for (int mt = 0; mt < 4; mt++)
        #pragma unroll
        for (int nt = 0; nt < 8; nt++)
            #pragma unroll
            for (int q = 0; q < 4; q++) acc[mt][nt][q] = 0.f;

    int ntiles = ic_total >> 5;

    // tile copy: rows k = r*4 + wid, 16B per thread-row for W and X
    #define COPY_TILE(K0, S) do {                                              \
        float* Wd = Wt0 + (S)*4096;                                           \
        float* Xd = Xt0 + (S)*4096;                                           \
        _Pragma("unroll")                                                      \
        for (int r = 0; r < 8; r++) {                                          \
            int k = r*4 + wid;                                                 \
            int col = (lane*4) ^ ((k & 3)*8);                                  \
            const float* wsrc = wbase + (size_t)((K0) + k)*oc_total;           \
            CP16((unsigned)__cvta_generic_to_shared(Wd + k*128 + col), wsrc);  \
            int c = (K0) + k;                                                  \
            const float* xsrc;                                                 \
            if (c < ic1log) {                                                  \
                int ce = wrap ? (c & 255) : c;                                 \
                xsrc = in1b + (size_t)ce*SPA;                                  \
            } else {                                                           \
                xsrc = in2b + (size_t)(c - ic1log)*SPA;                        \
            }                                                                  \
            CP16((unsigned)__cvta_generic_to_shared(Xd + k*128 + col),         \
                 xsrc + lane*4);                                               \
        }                                                                      \
    } while (0)

    COPY_TILE(0, 0);
    asm volatile("cp.async.commit_group;\n");

    #pragma unroll 1
    for (int t = 0; t < ntiles; t++) {
        if (t + 1 < ntiles) {
            COPY_TILE((t+1)*32, (t+1)&1);
            asm volatile("cp.async.commit_group;\n");
            asm volatile("cp.async.wait_group 1;\n");
        } else {
            asm volatile("cp.async.wait_group 0;\n");
        }
        __syncthreads();
        const float* Wk = Wt0 + (t&1)*4096;
        const float* Xk = Xt0 + (t&1)*4096;
        #pragma unroll
        for (int step = 0; step < 4; step++) {
            int r0 = step*8 + tig, r1 = r0 + 4;
            uint32_t a[4][4], bf[8][2];
            #pragma unroll
            for (int mt = 0; mt < 4; mt++) {
                int m = warpm0 + mt*16 + gid;
                a[mt][0] = __float_as_uint(Wk[r0*128 + ( m      ^ swz)]);
                a[mt][1] = __float_as_uint(Wk[r0*128 + ((m + 8) ^ swz)]);
                a[mt][2] = __float_as_uint(Wk[r1*128 + ( m      ^ swz)]);
                a[mt][3] = __float_as_uint(Wk[r1*128 + ((m + 8) ^ swz)]);
            }
            #pragma unroll
            for (int nt = 0; nt < 8; nt++) {
                int n = warpn0 + nt*8 + gid;
                bf[nt][0] = f2tf(Xk[r0*128 + (n ^ swz)]);
                bf[nt][1] = f2tf(Xk[r1*128 + (n ^ swz)]);
            }
            #pragma unroll
            for (int mt = 0; mt < 4; mt++)
                #pragma unroll
                for (int nt = 0; nt < 8; nt++) {
                    asm volatile(
                        "mma.sync.aligned.m16n8k8.row.col.f32.tf32.tf32.f32 "
                        "{%0,%1,%2,%3}, {%4,%5,%6,%7}, {%8,%9}, {%0,%1,%2,%3};"
                        : "+f"(acc[mt][nt][0]), "+f"(acc[mt][nt][1]),
                          "+f"(acc[mt][nt][2]), "+f"(acc[mt][nt][3])
                        : "r"(a[mt][0]), "r"(a[mt][1]), "r"(a[mt][2]), "r"(a[mt][3]),
                          "r"(bf[nt][0]), "r"(bf[nt][1]));
                }
        }
        __syncthreads();
    }

    // epilogue
    #pragma unroll
    for (int mt = 0; mt < 4; mt++) {
        #pragma unroll
        for (int rr = 0; rr < 2; rr++) {
            int m = oc0 + warpm0 + mt*16 + rr*8 + gid;
            float bi = bias ? bias[m] : 0.f;
            size_t ob = ((size_t)b*oc_total + m)*SPA + p0 + warpn0 + tig*2;
            #pragma unroll
            for (int nt = 0; nt < 8; nt++) {
                float2 v;
                v.x = acc[mt][nt][rr*2 + 0] + bi;
                v.y = acc[mt][nt][rr*2 + 1] + bi;
                if (res) {
                    float2 rv = *(const float2*)(res + ob + nt*8);
                    v.x += rv.x; v.y += rv.y;
                }
                *(float2*)(out + ob + nt*8) = v;
            }
        }
    }
}

// ------------------------- fused L2 normalize (q and k) ---------------------
__global__ void l2norm2_kernel(float* __restrict__ qkv) {
    int gr = blockIdx.x * 32 + (threadIdx.x >> 3);
    int l8 = threadIdx.x & 7;
    int off0 = (gr < 524288) ? 0 : 256;
    int r = gr & 524287;
    int b = r >> 16, ch = (r >> 8) & 255, hh = r & 255;
    size_t base = (((size_t)b*768 + off0 + ch)*256 + hh)*32 + l8*4;
    float4 v = *(float4*)(qkv + base);
    float sq = v.x*v.x + v.y*v.y + v.z*v.z + v.w*v.w;
    sq += __shfl_xor_sync(0xffffffffu, sq, 1);
    sq += __shfl_xor_sync(0xffffffffu, sq, 2);
    sq += __shfl_xor_sync(0xffffffffu, sq, 4);
    float inv = 1.f / fmaxf(sqrtf(sq), 1e-12f);
    v.x *= inv; v.y *= inv; v.z *= inv; v.w *= inv;
    *(float4*)(qkv + base) = v;
}

// ------------------------- q_probe[bh][w] = sum_{dh,hh} qn -------------------
__global__ void probe_kernel(const float* __restrict__ qkv, float* __restrict__ probe) {
    int bh = blockIdx.x;
    int b = bh >> 3, head = bh & 7;
    int tid = threadIdx.x;
    int w = tid & 31, grp = tid >> 5;
    const float* qb = qkv + ((size_t)b*768 + head*32)*SPA;
    float s = 0.f;
    for (int idx = grp; idx < 32*256; idx += 8)
        s += qb[(size_t)idx*32 + w];
    __shared__ float red[8][32];
    red[grp][w] = s;
    __syncthreads();
    if (tid < 32) {
        float t = 0.f;
        #pragma unroll
        for (int g = 0; g < 8; g++) t += red[g][tid];
        probe[bh*32 + tid] = t;
    }
}

// ------------------------- top-k selection + gather -------------------------
__global__ void select_kernel(const float* __restrict__ qkv,
                              const float* __restrict__ probe,
                              float* __restrict__ k2, float* __restrict__ v2) {
    int bh = blockIdx.x;
    int b = bh >> 3, head = bh & 7;
    int tid = threadIdx.x;
    int w = tid & 31;
    const float* kb = qkv + ((size_t)b*768 + 256 + head*32)*SPA;
    const float* vb = qkv + ((size_t)b*768 + 512 + head*32)*SPA;
    __shared__ float pr[32];
    __shared__ float kh[32][32];
    __shared__ float sh[32];
    __shared__ int   sel_dh[8];
    __shared__ float ks2[256][33];
    __shared__ float sw[256];
    __shared__ int   sel_hh[8];
    if (tid < 32) pr[tid] = probe[bh*32 + tid];
    for (int dh = tid >> 5; dh < 32; dh += 8) {
        float s = 0.f;
        for (int hh = 0; hh < 256; hh++)
            s += kb[(size_t)dh*8192 + hh*32 + w];
        kh[dh][w] = s;
    }
    __syncthreads();
    if (tid < 32) {
        float s = 0.f;
        #pragma unroll
        for (int w2 = 0; w2 < 32; w2++) s += pr[w2] * kh[tid][w2];
        sh[tid] = s;
    }
    __syncthreads();
    if (tid == 0) {
        unsigned used = 0u;
        for (int j = 0; j < 8; j++) {
            int best = -1; float bv = -FLT_MAX;
            for (int d2 = 0; d2 < 32; d2++) {
                if ((used >> d2) & 1u) continue;
                if (best < 0 || sh[d2] > bv) { best = d2; bv = sh[d2]; }
            }
            used |= 1u << best;
            sel_dh[j] = best;
        }
    }
    __syncthreads();
    for (int hh = tid >> 5; hh < 256; hh += 8) {
        float s = 0.f;
        #pragma unroll
        for (int j = 0; j < 8; j++)
            s += kb[(size_t)sel_dh[j]*8192 + hh*32 + w];
        ks2[hh][w] = s;
    }
    __syncthreads();
    {
        float s = 0.f;
        #pragma unroll
        for (int w2 = 0; w2 < 32; w2++) s += pr[w2] * ks2[tid][w2];
        sw[tid] = s;
    }
    __syncthreads();
    if (tid == 0) {
        unsigned um[8] = {0,0,0,0,0,0,0,0};
        for (int j = 0; j < 8; j++) {
            int best = -1; float bv = -FLT_MAX;
            for (int h2 = 0; h2 < 256; h2++) {
                if ((um[h2 >> 5] >> (h2 & 31)) & 1u) continue;
                if (best < 0 || sw[h2] > bv) { best = h2; bv = sw[h2]; }
            }
            um[best >> 5] |= 1u << (best & 31);
            sel_hh[j] = best;
        }
    }
    __syncthreads();
    for (int j = tid >> 5; j < 64; j += 8) {
        int jd = j >> 3, jw = j & 7;
        size_t src = (size_t)sel_dh[jd]*8192 + sel_hh[jw]*32 + w;
        k2[(size_t)(bh*64 + j)*32 + w] = kb[src];
        v2[(size_t)(bh*64 + j)*32 + w] = vb[src];
    }
}

// ------------------------- attention (64 keys) + transpose write ------------
__global__ void attn_kernel(const float* __restrict__ qkv,
                            const float* __restrict__ k2,
                            const float* __restrict__ v2,
                            float* __restrict__ o_r) {
    __shared__ float k2s[64*33];
    __shared__ float v2s[64*33];
    __shared__ float os[32*129];
    int bh = blockIdx.y;
    int b = bh >> 3, head = bh & 7;
    int i0 = blockIdx.x * 128;
    int tid = threadIdx.x;
    int lane = tid & 31, wid = tid >> 5;
    #pragma unroll
    for (int r = 0; r < 8; r++) {
        int jj = wid + r*8;
        k2s[jj*33 + lane] = k2[(size_t)(bh*64 + jj)*32 + lane];
        v2s[jj*33 + lane] = v2[(size_t)(bh*64 + jj)*32 + lane];
    }
    __syncthreads();
    const float* qb = qkv + ((size_t)b*768 + head*32)*SPA;
    for (int it = 0; it < 16; it++) {
        int li = wid*16 + it;
        int i = i0 + li;
        float qv = qb[(size_t)i*32 + lane];
        float s0 = 0.f, s1 = 0.f;
        #pragma unroll
        for (int d = 0; d < 32; d++) {
            float qd = __shfl_sync(0xffffffffu, qv, d);
            s0 = fmaf(qd, k2s[lane*33 + d], s0);
            s1 = fmaf(qd, k2s[(lane+32)*33 + d], s1);
        }
        float mx = fmaxf(s0, s1);
        #pragma unroll
        for (int o = 16; o; o >>= 1) mx = fmaxf(mx, __shfl_xor_sync(0xffffffffu, mx, o));
        float p0 = expf(s0 - mx), p1 = expf(s1 - mx);
        float ssm = p0 + p1;
        #pragma unroll
        for (int o = 16; o; o >>= 1) ssm += __shfl_xor_sync(0xffffffffu, ssm, o);
        float inv = 1.f / ssm;
        float ov = 0.f;
        #pragma unroll
        for (int j = 0; j < 32; j++) {
            float pa = __shfl_sync(0xffffffffu, p0, j);
            float pb = __shfl_sync(0xffffffffu, p1, j);
            ov = fmaf(pa, v2s[j*33 + lane], ov);
            ov = fmaf(pb, v2s[(j+32)*33 + lane], ov);
        }
        os[lane*129 + li] = ov * inv;
    }
    __syncthreads();
    #pragma unroll
    for (int dblk = 0; dblk < 4; dblk++) {
        int d = dblk*8 + wid;
        float* ob = o_r + ((size_t)b*256 + head*32 + d)*SPA + i0;
        #pragma unroll
        for (int cs = 0; cs < 4; cs++)
            ob[cs*32 + lane] = os[d*129 + cs*32 + lane];
    }
}

// ------------------------- depthwise 3x3 (SAME) -----------------------------
__global__ void dwconv3_kernel(const float* __restrict__ in, const float* __restrict__ w,
                               const float* __restrict__ bias, float* __restrict__ out) {
    int b = blockIdx.z;
    int c = blockIdx.y;
    int C = gridDim.y;
    int hh = blockIdx.x*8 + (threadIdx.x >> 5);
    int ww = threadIdx.x & 31;
    const float* ib = in + ((size_t)b*C + c)*SPA;
    float s = bias[c];
    #pragma unroll
    for (int dy = 0; dy < 3; dy++) {
        int y = hh + dy - 1;
        if (y < 0 || y >= HDIM) continue;
        #pragma unroll
        for (int dx = 0; dx < 3; dx++) {
            int x2 = ww + dx - 1;
            if (x2 < 0 || x2 >= WDIM) continue;
            s = fmaf(ib[y*WDIM + x2], w[c*9 + dy*3 + dx], s);
        }
    }
    out[((size_t)b*C + c)*SPA + hh*WDIM + ww] = s;
}

// ------------------------- instance norm (+gelu, +residual) -----------------
__global__ void inorm_kernel(const float* __restrict__ in, const float* __restrict__ add,
                             float* __restrict__ out, int mode) {
    size_t base = (size_t)blockIdx.x * SPA;
    int tid = threadIdx.x;
    float v[32];
    double s = 0.0, s2 = 0.0;
    #pragma unroll
    for (int j = 0; j < 32; j++) {
        float t = in[base + j*256 + tid];
        v[j] = t;
        s += t; s2 += (double)t*(double)t;
    }
    __shared__ double rs[8], rq[8];
    __shared__ float mv[2];
    #pragma unroll
    for (int o = 16; o; o >>= 1) {
        s  += __shfl_xor_sync(0xffffffffu, s, o);
        s2 += __shfl_xor_sync(0xffffffffu, s2, o);
    }
    if ((tid & 31) == 0) { rs[tid >> 5] = s; rq[tid >> 5] = s2; }
    __syncthreads();
    if (tid == 0) {
        double ts = 0.0, tq = 0.0;
        #pragma unroll
        for (int g = 0; g < 8; g++) { ts += rs[g]; tq += rq[g]; }
        double m   = ts / (double)SPA;
        double var = tq / (double)SPA - m*m;
        mv[0] = (float)m;
        mv[1] = (float)(1.0 / sqrt(var + 1e-5));
    }
    __syncthreads();
    float m = mv[0], r = mv[1];
    #pragma unroll
    for (int j = 0; j < 32; j++) {
        float t = (v[j] - m) * r;
        if (mode >= 1) t = 0.5f * t * (1.f + erff(t * 0.70710678118654752f));
        if (mode == 2) t += add[base + j*256 + tid];
        out[base + j*256 + tid] = t;
    }
}

// ------------------------- host orchestration -------------------------------
extern "C" void kernel_launch(void* const* d_in, const int* in_sizes, int n_in,
                              void* d_out, int out_size) {
    (void)in_sizes; (void)n_in; (void)out_size;
    const float* x      = (const float*)d_in[0];
    const float* cln_g  = (const float*)d_in[1];
    const float* cln_b  = (const float*)d_in[2];
    const float* w_qkv  = (const float*)d_in[3];
    const float* w_out  = (const float*)d_in[4];
    const float* b_out  = (const float*)d_in[5];
    const float* w_dw   = (const float*)d_in[6];
    const float* b_dw   = (const float*)d_in[7];
    const float* w_comb = (const float*)d_in[8];
    const float* b_comb = (const float*)d_in[9];
    const float* w_ff1  = (const float*)d_in[10];
    const float* b_ff1  = (const float*)d_in[11];
    const float* w_ffdw = (const float*)d_in[12];
    const float* b_ffdw = (const float*)d_in[13];
    const float* w_ff2  = (const float*)d_in[14];
    const float* b_ff2  = (const float*)d_in[15];
    float* out = (float*)d_out;

    float *p_xn, *p_xs, *p_qkv, *p_or, *p_attn, *p_conv, *p_comb, *p_ff1, *p_ffdw, *p_ff2;
    float *p_probe, *p_k2, *p_v2, *p_wt;
    cudaGetSymbolAddress((void**)&p_xn,   g_xn);
    cudaGetSymbolAddress((void**)&p_xs,   g_xs);
    cudaGetSymbolAddress((void**)&p_qkv,  g_qkv);
    cudaGetSymbolAddress((void**)&p_or,   g_or);
    cudaGetSymbolAddress((void**)&p_attn, g_attn);
    cudaGetSymbolAddress((void**)&p_conv, g_conv);
    cudaGetSymbolAddress((void**)&p_comb, g_comb);
    cudaGetSymbolAddress((void**)&p_ff1,  g_ff1);
    cudaGetSymbolAddress((void**)&p_ffdw, g_ffdw);
    cudaGetSymbolAddress((void**)&p_ff2,  g_ff2);
    cudaGetSymbolAddress((void**)&p_probe,g_probe);
    cudaGetSymbolAddress((void**)&p_k2,   g_k2);
    cudaGetSymbolAddress((void**)&p_v2,   g_v2);
    cudaGetSymbolAddress((void**)&p_wt,   g_wt);

    static bool attr_set = false;
    if (!attr_set) {
        cudaFuncSetAttribute(gemm_tf32,
            cudaFuncAttributeMaxDynamicSharedMemorySize, 65536);
        attr_set = true;
    }
    const int GSM = 65536;

    // 0) weight transposes (+ tf32 rounding)
    transpose_kernel<<<dim3(8, 8),  256>>>(w_out,  p_wt + WT_OUT,  256, 256);
    transpose_kernel<<<dim3(16, 8), 256>>>(w_comb, p_wt + WT_COMB, 256, 512);
    transpose_kernel<<<dim3(8, 32), 256>>>(w_ff1,  p_wt + WT_FF1,  1024, 256);
    transpose_kernel<<<dim3(32, 8), 256>>>(w_ff2,  p_wt + WT_FF2,  256, 1024);
    transpose_split_qkv<<<dim3(8, 24), 256>>>(w_qkv, p_wt + WT_QKV);

    // 1) channel LN -> xn; then split xn into tf32 big (in place) + small
    chan_ln_kernel<<<dim3(HDIM, BATCH), 256>>>(x, cln_g, cln_b, p_xn);
    split_x_kernel<<<16384, 256>>>(p_xn, p_xs, BATCH*CDIM*SPA/4);

    // 2) qkv = W*xn via exact tf32 split: K=768 GEMM over [Wb;Ws;Wb] x [xb;xb;xs]
    gemm_tf32<<<dim3(6, 64, 8), 128, GSM>>>(p_xn, p_xs, 512, 256, 768, 1,
        p_wt + WT_QKV, nullptr, nullptr, p_qkv, 768);

    // 3) L2-normalize q and k
    l2norm2_kernel<<<32768, 256>>>(p_qkv);
    // 4) q_probe
    probe_kernel<<<NBH, 256>>>(p_qkv, p_probe);
    // 5) top-k selection + gather
    select_kernel<<<NBH, 256>>>(p_qkv, p_probe, p_k2, p_v2);
    // 6) attention + transpose
    attn_kernel<<<dim3(64, NBH), 256>>>(p_qkv, p_k2, p_v2, p_or);
    // 7) attn_branch = conv1x1(o_r, w_out, b_out)
    gemm_tf32<<<dim3(2, 64, 8), 128, GSM>>>(p_or, nullptr, 256, 256, 256, 0,
        p_wt + WT_OUT, b_out, nullptr, p_attn, 256);
    // 8) conv_branch = dwconv3(x)
    dwconv3_kernel<<<dim3(32, 256, 8), 256>>>(x, w_dw, b_dw, p_conv);
    // 9) comb = conv1x1(concat(attn, conv)) + x
    gemm_tf32<<<dim3(2, 64, 8), 128, GSM>>>(p_attn, p_conv, 256, 256, 512, 0,
        p_wt + WT_COMB, b_comb, x, p_comb, 256);
    // 10) ff1
    gemm_tf32<<<dim3(8, 64, 8), 128, GSM>>>(p_comb, nullptr, 256, 256, 256, 0,
        p_wt + WT_FF1, b_ff1, nullptr, p_ff1, 1024);
    // 11) h1 = gelu(inorm(ff1))
    inorm_kernel<<<BATCH*FFI, 256>>>(p_ff1, nullptr, p_ff1, 1);
    // 12) ffdw = dwconv3(h1)
    dwconv3_kernel<<<dim3(32, 1024, 8), 256>>>(p_ff1, w_ffdw, b_ffdw, p_ffdw);
    // 13) h2 = h1 + gelu(inorm(ffdw))
    inorm_kernel<<<BATCH*FFI, 256>>>(p_ffdw, p_ff1, p_ffdw, 2);
    // 14) ff2
    gemm_tf32<<<dim3(2, 64, 8), 128, GSM>>>(p_ffdw, nullptr, 1024, 1024, 1024, 0,
        p_wt + WT_FF2, b_ff2, nullptr, p_ff2, 256);
    // 15) out = inorm(ff2)
    inorm_kernel<<<BATCH*CDIM, 256>>>(p_ff2, nullptr, out, 0);
}

// round 14
// speedup vs baseline: 1.0005x; 1.0005x over previous
#include <cuda_runtime.h>
#include <math.h>
#include <float.h>
#include <stdint.h>

#define BATCH 8
#define CDIM  256
#define HDIM  256
#define WDIM  32
#define SPA   8192      // HDIM*WDIM
#define FFI   1024
#define NBH   64        // BATCH*HEADS

// ------------------------- scratch (device globals) -------------------------
__device__ float g_xn  [BATCH*CDIM*SPA];
__device__ float g_xs  [BATCH*CDIM*SPA];
__device__ float g_qkv [BATCH*3*CDIM*SPA];
__device__ float g_or  [BATCH*CDIM*SPA];
__device__ float g_attn[BATCH*CDIM*SPA];
__device__ float g_conv[BATCH*CDIM*SPA];
__device__ float g_comb[BATCH*CDIM*SPA];
__device__ float g_ff1 [BATCH*FFI*SPA];
__device__ float g_ffdw[BATCH*FFI*SPA];
__device__ float g_ff2 [BATCH*CDIM*SPA];
__device__ float g_probe[NBH*32];
__device__ float g_k2 [NBH*64*32];
__device__ float g_v2 [NBH*64*32];
__device__ float g_wt [1310720];   // transposed (K-major), tf32-rounded weights

// wt offsets (floats)
#define WT_OUT  0          // 256 x 256
#define WT_COMB 65536      // 512 x 256
#define WT_FF1  196608     // 256 x 1024
#define WT_FF2  458752     // 1024 x 256
#define WT_QKV  720896     // 768 x 768  ([Wb; Ws; Wb] rows)

__device__ __forceinline__ uint32_t f2tf(float f) {
    uint32_t r;
    asm("cvt.rna.tf32.f32 %0, %1;" : "=r"(r) : "f"(f));
    return r;
}

// ------------------------- weight transpose (+ tf32 round) ------------------
__global__ void transpose_kernel(const float* __restrict__ w, float* __restrict__ wt,
                                 int M, int K) {
    __shared__ float t[32][33];
    int k0 = blockIdx.x*32, m0 = blockIdx.y*32;
    int tx = threadIdx.x & 31, ty = threadIdx.x >> 5;   // 32 x 8
    #pragma unroll
    for (int r = 0; r < 4; r++)
        t[ty + r*8][tx] = w[(size_t)(m0 + ty + r*8)*K + k0 + tx];
    __syncthreads();
    #pragma unroll
    for (int r = 0; r < 4; r++)
        wt[(size_t)(k0 + ty + r*8)*M + m0 + tx] =
            __uint_as_float(f2tf(t[tx][ty + r*8]));
}

// qkv weight: [768][256] -> wq [768 rows][768 cols]: rows 0-255 = Wb^T,
// 256-511 = Ws^T, 512-767 = Wb^T (for the K=768 split GEMM).
__global__ void transpose_split_qkv(const float* __restrict__ w, float* __restrict__ wq) {
    __shared__ float t[32][33];
    int k0 = blockIdx.x*32, m0 = blockIdx.y*32;   // k over 256, m over 768
    int tx = threadIdx.x & 31, ty = threadIdx.x >> 5;
    #pragma unroll
    for (int r = 0; r < 4; r++)
        t[ty + r*8][tx] = w[(size_t)(m0 + ty + r*8)*256 + k0 + tx];
    __syncthreads();
    #pragma unroll
    for (int r = 0; r < 4; r++) {
        int k = k0 + ty + r*8;
        int m = m0 + tx;
        float v = t[tx][ty + r*8];
        float big = __uint_as_float(f2tf(v));
        float sml = __uint_as_float(f2tf(v - big));
        wq[(size_t)k*768 + m]         = big;
        wq[(size_t)(256 + k)*768 + m] = sml;
        wq[(size_t)(512 + k)*768 + m] = big;
    }
}

// ------------------------- split X into tf32 big/small (in place) -----------
__global__ void split_x_kernel(float* __restrict__ xb, float* __restrict__ xs, int n4) {
    int i = blockIdx.x*blockDim.x + threadIdx.x;
    if (i >= n4) return;
    float4 v = ((float4*)xb)[i];
    float4 b, s;
    b.x = __uint_as_float(f2tf(v.x)); s.x = __uint_as_float(f2tf(v.x - b.x));
    b.y = __uint_as_float(f2tf(v.y)); s.y = __uint_as_float(f2tf(v.y - b.y));
    b.z = __uint_as_float(f2tf(v.z)); s.z = __uint_as_float(f2tf(v.z - b.z));
    b.w = __uint_as_float(f2tf(v.w)); s.w = __uint_as_float(f2tf(v.w - b.w));
    ((float4*)xb)[i] = b;
    ((float4*)xs)[i] = s;
}

// ------------------------- channel LayerNorm (axis=C) -----------------------
__global__ void chan_ln_kernel(const float* __restrict__ x,
                               const float* __restrict__ gma,
                               const float* __restrict__ bta,
                               float* __restrict__ xn) {
    __shared__ float  xsm[CDIM*32];
    __shared__ double ssum[8][32];
    __shared__ double ssq [8][32];
    __shared__ float  mbuf[32], rbuf[32];
    int b = blockIdx.y, hh = blockIdx.x;
    int tid = threadIdx.x;
    int cg = tid >> 5, p = tid & 31;
    const float* xb = x + (size_t)b*CDIM*SPA + hh*WDIM + p;
    double s = 0.0, s2 = 0.0;
    #pragma unroll
    for (int j = 0; j < 32; j++) {
        int c = cg*32 + j;
        float v = xb[(size_t)c*SPA];
        xsm[c*32 + p] = v;
        s += v; s2 += (double)v*(double)v;
    }
    ssum[cg][p] = s; ssq[cg][p] = s2;
    __syncthreads();
    if (tid < 32) {
        double ts = 0.0, tq = 0.0;
        #pragma unroll
        for (int g = 0; g < 8; g++) { ts += ssum[g][tid]; tq += ssq[g][tid]; }
        double m   = ts / 256.0;
        double var = tq / 256.0 - m*m;
        mbuf[tid] = (float)m;
        rbuf[tid] = (float)(1.0 / sqrt(var + 1e-5));
    }
    __syncthreads();
    float m = mbuf[p], r = rbuf[p];
    float* xo = xn + (size_t)b*CDIM*SPA + hh*WDIM + p;
    #pragma unroll
    for (int j = 0; j < 32; j++) {
        int c = cg*32 + j;
        xo[(size_t)c*SPA] = (xsm[c*32 + p] - m) * r * gma[c] + bta[c];
    }
}

// ------------------------- tf32 GEMM: 128x128x32, 4 warps, 64x64 warp tile --
// out[b,m,n] = bias[m] + sum_c wt[c][m] * X[b,c,n] (+res). X = concat(in1,in2)
// over logical channels [0,ic1log) -> in1 (row = wrap ? c&255 : c), rest -> in2.
// wt rows pre-rounded to tf32. cp.async double-buffered staging.
#define CP16(dst, src) asm volatile("cp.async.ca.shared.global [%0], [%1], 16;\n" \
    :: "r"(dst), "l"(src))

__global__ void __launch_bounds__(128)
gemm_tf32(const float* __restrict__ in1, const float* __restrict__ in2,
          int ic1log, int ic1p, int ic_total, int wrap,
          const float* __restrict__ wt, const float* __restrict__ bias,
          const float* __restrict__ res, float* __restrict__ out,
          int oc_total) {
    extern __shared__ float sm[];
    float* Wt0 = sm;              // [2][32*128]
    float* Xt0 = sm + 8192;       // [2][32*128]

    int oc0 = blockIdx.x * 128;
    int p0  = blockIdx.y * 128;
    int b   = blockIdx.z;
    int tid = threadIdx.x;
    int lane = tid & 31, wid = tid >> 5;
    int gid = lane >> 2, tig = lane & 3;
    int warpm0 = (wid & 1) * 64;
    int warpn0 = (wid >> 1) * 64;
    int swz = tig * 8;

    const float* in1b = in1 + (size_t)b*ic1p*SPA + p0;
    const float* in2b = in2 ? (in2 + (size_t)b*(ic_total - ic1log)*SPA + p0)
                            : (const float*)0;
    const float* wbase = wt + oc0 + lane*4;

    float acc[4][8][4];
    #pragma unroll
    for (int mt = 0; mt < 4; mt++)
        #pragma unroll
        for (int nt = 0; nt < 8; nt++)
            #pragma unroll
            for (int q = 0; q < 4; q++) acc[mt][nt][q] = 0.f;

    int ntiles = ic_total >> 5;

    // tile copy: rows k = r*4 + wid, 16B per thread-row for W and X
    #define COPY_TILE(K0, S) do {                                              \
        float* Wd = Wt0 + (S)*4096;                                           \
        float* Xd = Xt0 + (S)*4096;                                           \
        _Pragma("unroll")                                                      \
        for (int r = 0; r < 8; r++) {                                          \
            int k = r*4 + wid;                                                 \
            int col = (lane*4) ^ ((k & 3)*8);                                  \
            const float* wsrc = wbase + (size_t)((K0) + k)*oc_total;           \
            CP16((unsigned)__cvta_generic_to_shared(Wd + k*128 + col), wsrc);  \
            int c = (K0) + k;                                                  \
            const float* xsrc;                                                 \
            if (c < ic1log) {                                                  \
                int ce = wrap ? (c & 255) : c;                                 \
                xsrc = in1b + (size_t)ce*SPA;                                  \
            } else {                                                           \
                xsrc = in2b + (size_t)(c - ic1log)*SPA;                        \
            }                                                                  \
            CP16((unsigned)__cvta_generic_to_shared(Xd + k*128 + col),         \
                 xsrc + lane*4);                                               \
        }                                                                      \
    } while (0)

    COPY_TILE(0, 0);
    asm volatile("cp.async.commit_group;\n");

    #pragma unroll 1
    for (int t = 0; t < ntiles; t++) {
        if (t + 1 < ntiles) {
            COPY_TILE((t+1)*32, (t+1)&1);
            asm volatile("cp.async.commit_group;\n");
            asm volatile("cp.async.wait_group 1;\n");
        } else {
            asm volatile("cp.async.wait_group 0;\n");
        }
        __syncthreads();
        const float* Wk = Wt0 + (t&1)*4096;
        const float* Xk = Xt0 + (t&1)*4096;
        #pragma unroll
        for (int step = 0; step < 4; step++) {
            int r0 = step*8 + tig, r1 = r0 + 4;
            uint32_t a[4][4], bf[8][2];
            #pragma unroll
            for (int mt = 0; mt < 4; mt++) {
                int m = warpm0 + mt*16 + gid;
                a[mt][0] = __float_as_uint(Wk[r0*128 + ( m      ^ swz)]);
                a[mt][1] = __float_as_uint(Wk[r0*128 + ((m + 8) ^ swz)]);
                a[mt][2] = __float_as_uint(Wk[r1*128 + ( m      ^ swz)]);
                a[mt][3] = __float_as_uint(Wk[r1*128 + ((m + 8) ^ swz)]);
            }
            #pragma unroll
            for (int nt = 0; nt < 8; nt++) {
                int n = warpn0 + nt*8 + gid;
                bf[nt][0] = f2tf(Xk[r0*128 + (n ^ swz)]);
                bf[nt][1] = f2tf(Xk[r1*128 + (n ^ swz)]);
            }
            #pragma unroll
            for (int mt = 0; mt < 4; mt++)
                #pragma unroll
                for (int nt = 0; nt < 8; nt++) {
                    asm volatile(
                        "mma.sync.aligned.m16n8k8.row.col.f32.tf32.tf32.f32 "
                        "{%0,%1,%2,%3}, {%4,%5,%6,%7}, {%8,%9}, {%0,%1,%2,%3};"
                        : "+f"(acc[mt][nt][0]), "+f"(acc[mt][nt][1]),
                          "+f"(acc[mt][nt][2]), "+f"(acc[mt][nt][3])
                        : "r"(a[mt][0]), "r"(a[mt][1]), "r"(a[mt][2]), "r"(a[mt][3]),
                          "r"(bf[nt][0]), "r"(bf[nt][1]));
                }
        }
        __syncthreads();
    }

    // epilogue
    #pragma unroll
    for (int mt = 0; mt < 4; mt++) {
        #pragma unroll
        for (int rr = 0; rr < 2; rr++) {
            int m = oc0 + warpm0 + mt*16 + rr*8 + gid;
            float bi = bias ? bias[m] : 0.f;
            size_t ob = ((size_t)b*oc_total + m)*SPA + p0 + warpn0 + tig*2;
            #pragma unroll
            for (int nt = 0; nt < 8; nt++) {
                float2 v;
                v.x = acc[mt][nt][rr*2 + 0] + bi;
                v.y = acc[mt][nt][rr*2 + 1] + bi;
                if (res) {
                    float2 rv = *(const float2*)(res + ob + nt*8);
                    v.x += rv.x; v.y += rv.y;
                }
                *(float2*)(out + ob + nt*8) = v;
            }
        }
    }
}

// ------------------------- fused L2 normalize (q and k) ---------------------
__global__ void l2norm2_kernel(float* __restrict__ qkv) {
    int gr = blockIdx.x * 32 + (threadIdx.x >> 3);
    int l8 = threadIdx.x & 7;
    int off0 = (gr < 524288) ? 0 : 256;
    int r = gr & 524287;
    int b = r >> 16, ch = (r >> 8) & 255, hh = r & 255;
    size_t base = (((size_t)b*768 + off0 + ch)*256 + hh)*32 + l8*4;
    float4 v = *(float4*)(qkv + base);
    float sq = v.x*v.x + v.y*v.y + v.z*v.z + v.w*v.w;
    sq += __shfl_xor_sync(0xffffffffu, sq, 1);
    sq += __shfl_xor_sync(0xffffffffu, sq, 2);
    sq += __shfl_xor_sync(0xffffffffu, sq, 4);
    float inv = 1.f / fmaxf(sqrtf(sq), 1e-12f);
    v.x *= inv; v.y *= inv; v.z *= inv; v.w *= inv;
    *(float4*)(qkv + base) = v;
}

// ------------------------- q_probe[bh][w] = sum_{dh,hh} qn -------------------
__global__ void probe_kernel(const float* __restrict__ qkv, float* __restrict__ probe) {
    int bh = blockIdx.x;
    int b = bh >> 3, head = bh & 7;
    int tid = threadIdx.x;
    int w = tid & 31, grp = tid >> 5;
    const float* qb = qkv + ((size_t)b*768 + head*32)*SPA;
    float s = 0.f;
    for (int idx = grp; idx < 32*256; idx += 8)
        s += qb[(size_t)idx*32 + w];
    __shared__ float red[8][32];
    red[grp][w] = s;
    __syncthreads();
    if (tid < 32) {
        float t = 0.f;
        #pragma unroll
        for (int g = 0; g < 8; g++) t += red[g][tid];
        probe[bh*32 + tid] = t;
    }
}

// ------------------------- top-k selection + gather -------------------------
__global__ void select_kernel(const float* __restrict__ qkv,
                              const float* __restrict__ probe,
                              float* __restrict__ k2, float* __restrict__ v2) {
    int bh = blockIdx.x;
    int b = bh >> 3, head = bh & 7;
    int tid = threadIdx.x;
    int w = tid & 31;
    const float* kb = qkv + ((size_t)b*768 + 256 + head*32)*SPA;
    const float* vb = qkv + ((size_t)b*768 + 512 + head*32)*SPA;
    __shared__ float pr[32];
    __shared__ float kh[32][32];
    __shared__ float sh[32];
    __shared__ int   sel_dh[8];
    __shared__ float ks2[256][33];
    __shared__ float sw[256];
    __shared__ int   sel_hh[8];
    if (tid < 32) pr[tid] = probe[bh*32 + tid];
    for (int dh = tid >> 5; dh < 32; dh += 8) {
        float s = 0.f;
        for (int hh = 0; hh < 256; hh++)
            s += kb[(size_t)dh*8192 + hh*32 + w];
        kh[dh][w] = s;
    }
    __syncthreads();
    if (tid < 32) {
        float s = 0.f;
        #pragma unroll
        for (int w2 = 0; w2 < 32; w2++) s += pr[w2] * kh[tid][w2];
        sh[tid] = s;
    }
    __syncthreads();
    if (tid == 0) {
        unsigned used = 0u;
        for (int j = 0; j < 8; j++) {
            int best = -1; float bv = -FLT_MAX;
            for (int d2 = 0; d2 < 32; d2++) {
                if ((used >> d2) & 1u) continue;
                if (best < 0 || sh[d2] > bv) { best = d2; bv = sh[d2]; }
            }
            used |= 1u << best;
            sel_dh[j] = best;
        }
    }
    __syncthreads();
    for (int hh = tid >> 5; hh < 256; hh += 8) {
        float s = 0.f;
        #pragma unroll
        for (int j = 0; j < 8; j++)
            s += kb[(size_t)sel_dh[j]*8192 + hh*32 + w];
        ks2[hh][w] = s;
    }
    __syncthreads();
    {
        float s = 0.f;
        #pragma unroll
        for (int w2 = 0; w2 < 32; w2++) s += pr[w2] * ks2[tid][w2];
        sw[tid] = s;
    }
    __syncthreads();
    if (tid == 0) {
        unsigned um[8] = {0,0,0,0,0,0,0,0};
        for (int j = 0; j < 8; j++) {
            int best = -1; float bv = -FLT_MAX;
            for (int h2 = 0; h2 < 256; h2++) {
                if ((um[h2 >> 5] >> (h2 & 31)) & 1u) continue;
                if (best < 0 || sw[h2] > bv) { best = h2; bv = sw[h2]; }
            }
            um[best >> 5] |= 1u << (best & 31);
            sel_hh[j] = best;
        }
    }
    __syncthreads();
    for (int j = tid >> 5; j < 64; j += 8) {
        int jd = j >> 3, jw = j & 7;
        size_t src = (size_t)sel_dh[jd]*8192 + sel_hh[jw]*32 + w;
        k2[(size_t)(bh*64 + j)*32 + w] = kb[src];
        v2[(size_t)(bh*64 + j)*32 + w] = vb[src];
    }
}

// ------------------------- attention (64 keys) + transpose write ------------
__global__ void attn_kernel(const float* __restrict__ qkv,
                            const float* __restrict__ k2,
                            const float* __restrict__ v2,
                            float* __restrict__ o_r) {
    __shared__ float k2s[64*33];
    __shared__ float v2s[64*33];
    __shared__ float os[32*129];
    int bh = blockIdx.y;
    int b = bh >> 3, head = bh & 7;
    int i0 = blockIdx.x * 128;
    int tid = threadIdx.x;
    int lane = tid & 31, wid = tid >> 5;
    #pragma unroll
    for (int r = 0; r < 8; r++) {
        int jj = wid + r*8;
        k2s[jj*33 + lane] = k2[(size_t)(bh*64 + jj)*32 + lane];
        v2s[jj*33 + lane] = v2[(size_t)(bh*64 + jj)*32 + lane];
    }
    __syncthreads();
    const float* qb = qkv + ((size_t)b*768 + head*32)*SPA;
    for (int it = 0; it < 16; it++) {
        int li = wid*16 + it;
        int i = i0 + li;
        float qv = qb[(size_t)i*32 + lane];
        float s0 = 0.f, s1 = 0.f;
        #pragma unroll
        for (int d = 0; d < 32; d++) {
            float qd = __shfl_sync(0xffffffffu, qv, d);
            s0 = fmaf(qd, k2s[lane*33 + d], s0);
            s1 = fmaf(qd, k2s[(lane+32)*33 + d], s1);
        }
        float mx = fmaxf(s0, s1);
        #pragma unroll
        for (int o = 16; o; o >>= 1) mx = fmaxf(mx, __shfl_xor_sync(0xffffffffu, mx, o));
        float p0 = expf(s0 - mx), p1 = expf(s1 - mx);
        float ssm = p0 + p1;
        #pragma unroll
        for (int o = 16; o; o >>= 1) ssm += __shfl_xor_sync(0xffffffffu, ssm, o);
        float inv = 1.f / ssm;
        float ov = 0.f;
        #pragma unroll
        for (int j = 0; j < 32; j++) {
            float pa = __shfl_sync(0xffffffffu, p0, j);
            float pb = __shfl_sync(0xffffffffu, p1, j);
            ov = fmaf(pa, v2s[j*33 + lane], ov);
            ov = fmaf(pb, v2s[(j+32)*33 + lane], ov);
        }
        os[lane*129 + li] = ov * inv;
    }
    __syncthreads();
    #pragma unroll
    for (int dblk = 0; dblk < 4; dblk++) {
        int d = dblk*8 + wid;
        float* ob = o_r + ((size_t)b*256 + head*32 + d)*SPA + i0;
        #pragma unroll
        for (int cs = 0; cs < 4; cs++)
            ob[cs*32 + lane] = os[d*129 + cs*32 + lane];
    }
}

// ------------------------- depthwise 3x3 (SAME) -----------------------------
__global__ void dwconv3_kernel(const float* __restrict__ in, const float* __restrict__ w,
                               const float* __restrict__ bias, float* __restrict__ out) {
    int b = blockIdx.z;
    int c = blockIdx.y;
    int C = gridDim.y;
    int hh = blockIdx.x*8 + (threadIdx.x >> 5);
    int ww = threadIdx.x & 31;
    const float* ib = in + ((size_t)b*C + c)*SPA;
    float s = bias[c];
    #pragma unroll
    for (int dy = 0; dy < 3; dy++) {
        int y = hh + dy - 1;
        if (y < 0 || y >= HDIM) continue;
        #pragma unroll
        for (int dx = 0; dx < 3; dx++) {
            int x2 = ww + dx - 1;
            if (x2 < 0 || x2 >= WDIM) continue;
            s = fmaf(ib[y*WDIM + x2], w[c*9 + dy*3 + dx], s);
        }
    }
    out[((size_t)b*C + c)*SPA + hh*WDIM + ww] = s;
}

// ------------------------- instance norm (+gelu, +residual) -----------------
__global__ void inorm_kernel(const float* __restrict__ in, const float* __restrict__ add,
                             float* __restrict__ out, int mode) {
    size_t base = (size_t)blockIdx.x * SPA;
    int tid = threadIdx.x;
    float v[32];
    double s = 0.0, s2 = 0.0;
    #pragma unroll
    for (int j = 0; j < 32; j++) {
        float t = in[base + j*256 + tid];
        v[j] = t;
        s += t; s2 += (double)t*(double)t;
    }
    __shared__ double rs[8], rq[8];
    __shared__ float mv[2];
    #pragma unroll
    for (int o = 16; o; o >>= 1) {
        s  += __shfl_xor_sync(0xffffffffu, s, o);
        s2 += __shfl_xor_sync(0xffffffffu, s2, o);
    }
    if ((tid & 31) == 0) { rs[tid >> 5] = s; rq[tid >> 5] = s2; }
    __syncthreads();
    if (tid == 0) {
        double ts = 0.0, tq = 0.0;
        #pragma unroll
        for (int g = 0; g < 8; g++) { ts += rs[g]; tq += rq[g]; }
        double m   = ts / (double)SPA;
        double var = tq / (double)SPA - m*m;
        mv[0] = (float)m;
        mv[1] = (float)(1.0 / sqrt(var + 1e-5));
    }
    __syncthreads();
    float m = mv[0], r = mv[1];
    #pragma unroll
    for (int j = 0; j < 32; j++) {
        float t = (v[j] - m) * r;
        if (mode >= 1) t = 0.5f * t * (1.f + erff(t * 0.70710678118654752f));
        if (mode == 2) t += add[base + j*256 + tid];
        out[base + j*256 + tid] = t;
    }
}

// ------------------------- host orchestration -------------------------------
extern "C" void kernel_launch(void* const* d_in, const int* in_sizes, int n_in,
                              void* d_out, int out_size) {
    (void)in_sizes; (void)n_in; (void)out_size;
    const float* x      = (const float*)d_in[0];
    const float* cln_g  = (const float*)d_in[1];
    const float* cln_b  = (const float*)d_in[2];
    const float* w_qkv  = (const float*)d_in[3];
    const float* w_out  = (const float*)d_in[4];
    const float* b_out  = (const float*)d_in[5];
    const float* w_dw   = (const float*)d_in[6];
    const float* b_dw   = (const float*)d_in[7];
    const float* w_comb = (const float*)d_in[8];
    const float* b_comb = (const float*)d_in[9];
    const float* w_ff1  = (const float*)d_in[10];
    const float* b_ff1  = (const float*)d_in[11];
    const float* w_ffdw = (const float*)d_in[12];
    const float* b_ffdw = (const float*)d_in[13];
    const float* w_ff2  = (const float*)d_in[14];
    const float* b_ff2  = (const float*)d_in[15];
    float* out = (float*)d_out;

    float *p_xn, *p_xs, *p_qkv, *p_or, *p_attn, *p_conv, *p_comb, *p_ff1, *p_ffdw, *p_ff2;
    float *p_probe, *p_k2, *p_v2, *p_wt;
    cudaGetSymbolAddress((void**)&p_xn,   g_xn);
    cudaGetSymbolAddress((void**)&p_xs,   g_xs);
    cudaGetSymbolAddress((void**)&p_qkv,  g_qkv);
    cudaGetSymbolAddress((void**)&p_or,   g_or);
    cudaGetSymbolAddress((void**)&p_attn, g_attn);
    cudaGetSymbolAddress((void**)&p_conv, g_conv);
    cudaGetSymbolAddress((void**)&p_comb, g_comb);
    cudaGetSymbolAddress((void**)&p_ff1,  g_ff1);
    cudaGetSymbolAddress((void**)&p_ffdw, g_ffdw);
    cudaGetSymbolAddress((void**)&p_ff2,  g_ff2);
    cudaGetSymbolAddress((void**)&p_probe,g_probe);
    cudaGetSymbolAddress((void**)&p_k2,   g_k2);
    cudaGetSymbolAddress((void**)&p_v2,   g_v2);
    cudaGetSymbolAddress((void**)&p_wt,   g_wt);

    static bool attr_set = false;
    if (!attr_set) {
        cudaFuncSetAttribute(gemm_tf32,
            cudaFuncAttributeMaxDynamicSharedMemorySize, 65536);
        attr_set = true;
    }
    const int GSM = 65536;

    // 0) weight transposes (+ tf32 rounding)
    transpose_kernel<<<dim3(8, 8),  256>>>(w_out,  p_wt + WT_OUT,  256, 256);
    transpose_kernel<<<dim3(16, 8), 256>>>(w_comb, p_wt + WT_COMB, 256, 512);
    transpose_kernel<<<dim3(8, 32), 256>>>(w_ff1,  p_wt + WT_FF1,  1024, 256);
    transpose_kernel<<<dim3(32, 8), 256>>>(w_ff2,  p_wt + WT_FF2,  256, 1024);
    transpose_split_qkv<<<dim3(8, 24), 256>>>(w_qkv, p_wt + WT_QKV);

    // 1) channel LN -> xn; then split xn into tf32 big (in place) + small
    chan_ln_kernel<<<dim3(HDIM, BATCH), 256>>>(x, cln_g, cln_b, p_xn);
    split_x_kernel<<<16384, 256>>>(p_xn, p_xs, BATCH*CDIM*SPA/4);

    // 2) qkv = W*xn via exact tf32 split: K=768 GEMM over [Wb;Ws;Wb] x [xb;xb;xs]
    gemm_tf32<<<dim3(6, 64, 8), 128, GSM>>>(p_xn, p_xs, 512, 256, 768, 1,
        p_wt + WT_QKV, nullptr, nullptr, p_qkv, 768);

    // 3) L2-normalize q and k
    l2norm2_kernel<<<32768, 256>>>(p_qkv);
    // 4) q_probe
    probe_kernel<<<NBH, 256>>>(p_qkv, p_probe);
    // 5) top-k selection + gather
    select_kernel<<<NBH, 256>>>(p_qkv, p_probe, p_k2, p_v2);
    // 6) attention + transpose
    attn_kernel<<<dim3(64, NBH), 256>>>(p_qkv, p_k2, p_v2, p_or);
    // 7) attn_branch = conv1x1(o_r, w_out, b_out)
    gemm_tf32<<<dim3(2, 64, 8), 128, GSM>>>(p_or, nullptr, 256, 256, 256, 0,
        p_wt + WT_OUT, b_out, nullptr, p_attn, 256);
    // 8) conv_branch = dwconv3(x)
    dwconv3_kernel<<<dim3(32, 256, 8), 256>>>(x, w_dw, b_dw, p_conv);
    // 9) comb = conv1x1(concat(attn, conv)) + x
    gemm_tf32<<<dim3(2, 64, 8), 128, GSM>>>(p_attn, p_conv, 256, 256, 512, 0,
        p_wt + WT_COMB, b_comb, x, p_comb, 256);
    // 10) ff1
    gemm_tf32<<<dim3(8, 64, 8), 128, GSM>>>(p_comb, nullptr, 256, 256, 256, 0,
        p_wt + WT_FF1, b_ff1, nullptr, p_ff1, 1024);
    // 11) h1 = gelu(inorm(ff1))
    inorm_kernel<<<BATCH*FFI, 256>>>(p_ff1, nullptr, p_ff1, 1);
    // 12) ffdw = dwconv3(h1)
    dwconv3_kernel<<<dim3(32, 1024, 8), 256>>>(p_ff1, w_ffdw, b_ffdw, p_ffdw);
    // 13) h2 = h1 + gelu(inorm(ffdw))
    inorm_kernel<<<BATCH*FFI, 256>>>(p_ffdw, p_ff1, p_ffdw, 2);
    // 14) ff2
    gemm_tf32<<<dim3(2, 64, 8), 128, GSM>>>(p_ffdw, nullptr, 1024, 1024, 1024, 0,
        p_wt + WT_FF2, b_ff2, nullptr, p_ff2, 256);
    // 15) out = inorm(ff2)
    inorm_kernel<<<BATCH*CDIM, 256>>>(p_ff2, nullptr, out, 0);
}

// round 15
// speedup vs baseline: 1.1749x; 1.1743x over previous
#include <cuda_runtime.h>
#include <math.h>
#include <float.h>
#include <stdint.h>

#define BATCH 8
#define CDIM  256
#define HDIM  256
#define WDIM  32
#define SPA   8192      // HDIM*WDIM
#define FFI   1024
#define NBH   64        // BATCH*HEADS

// ------------------------- scratch (device globals) -------------------------
__device__ float g_xn  [BATCH*CDIM*SPA];   // tf32-rounded "big" part of xn
__device__ float g_xs  [BATCH*CDIM*SPA];   // tf32-rounded "small" residual
__device__ float g_qkv [BATCH*3*CDIM*SPA];
__device__ float g_or  [BATCH*CDIM*SPA];
__device__ float g_attn[BATCH*CDIM*SPA];
__device__ float g_conv[BATCH*CDIM*SPA];
__device__ float g_comb[BATCH*CDIM*SPA];
__device__ float g_ff1 [BATCH*FFI*SPA];
__device__ float g_ffdw[BATCH*FFI*SPA];
__device__ float g_ff2 [BATCH*CDIM*SPA];
__device__ float g_probe[NBH*32];
__device__ float g_k2 [NBH*64*32];
__device__ float g_v2 [NBH*64*32];
__device__ float g_wt [1310720];   // transposed (K-major), tf32-rounded weights
__device__ float g_s1 [BATCH*FFI]; // ff1 per-(b,c) sum
__device__ float g_s2 [BATCH*FFI]; // ff1 per-(b,c) sumsq

// wt offsets (floats)
#define WT_OUT  0          // 256 rows x 256
#define WT_COMB 65536      // 512 x 256
#define WT_FF1  196608     // 256 x 1024
#define WT_FF2  458752     // 1024 x 256
#define WT_QK   720896     // 768 x 512  ([Wb; Ws; Wb] rows, qk cols only)
#define WT_V    1114112    // 256 x 256

__device__ __forceinline__ uint32_t f2tf(float f) {
    uint32_t r;
    asm("cvt.rna.tf32.f32 %0, %1;" : "=r"(r) : "f"(f));
    return r;
}

// ------------------------- weight transpose (+ tf32 round) ------------------
__global__ void transpose_kernel(const float* __restrict__ w, float* __restrict__ wt,
                                 int M, int K) {
    __shared__ float t[32][33];
    int k0 = blockIdx.x*32, m0 = blockIdx.y*32;
    int tx = threadIdx.x & 31, ty = threadIdx.x >> 5;   // 32 x 8
    #pragma unroll
    for (int r = 0; r < 4; r++)
        t[ty + r*8][tx] = w[(size_t)(m0 + ty + r*8)*K + k0 + tx];
    __syncthreads();
    #pragma unroll
    for (int r = 0; r < 4; r++)
        wt[(size_t)(k0 + ty + r*8)*M + m0 + tx] =
            __uint_as_float(f2tf(t[tx][ty + r*8]));
}

// qk part of qkv weight: rows m<512 -> wq [768 K-rows][512 cols]:
// rows 0-255 = Wb^T, 256-511 = Ws^T, 512-767 = Wb^T.
__global__ void transpose_split_qk(const float* __restrict__ w, float* __restrict__ wq) {
    __shared__ float t[32][33];
    int k0 = blockIdx.x*32, m0 = blockIdx.y*32;   // k over 256, m over 512
    int tx = threadIdx.x & 31, ty = threadIdx.x >> 5;
    #pragma unroll
    for (int r = 0; r < 4; r++)
        t[ty + r*8][tx] = w[(size_t)(m0 + ty + r*8)*256 + k0 + tx];
    __syncthreads();
    #pragma unroll
    for (int r = 0; r < 4; r++) {
        int k = k0 + ty + r*8;
        int m = m0 + tx;
        float v = t[tx][ty + r*8];
        float big = __uint_as_float(f2tf(v));
        float sml = __uint_as_float(f2tf(v - big));
        wq[(size_t)k*512 + m]         = big;
        wq[(size_t)(256 + k)*512 + m] = sml;
        wq[(size_t)(512 + k)*512 + m] = big;
    }
}

__global__ void zero_stats(float* __restrict__ s1, float* __restrict__ s2) {
    int i = blockIdx.x*256 + threadIdx.x;
    if (i < BATCH*FFI) { s1[i] = 0.f; s2[i] = 0.f; }
}

// ------------------------- channel LayerNorm (axis=C) + tf32 split ----------
__global__ void chan_ln_kernel(const float* __restrict__ x,
                               const float* __restrict__ gma,
                               const float* __restrict__ bta,
                               float* __restrict__ xb_out,
                               float* __restrict__ xs_out) {
    __shared__ float  xsm[CDIM*32];
    __shared__ double ssum[8][32];
    __shared__ double ssq [8][32];
    __shared__ float  mbuf[32], rbuf[32];
    int b = blockIdx.y, hh = blockIdx.x;
    int tid = threadIdx.x;
    int cg = tid >> 5, p = tid & 31;
    const float* xbp = x + (size_t)b*CDIM*SPA + hh*WDIM + p;
    double s = 0.0, s2 = 0.0;
    #pragma unroll
    for (int j = 0; j < 32; j++) {
        int c = cg*32 + j;
        float v = xbp[(size_t)c*SPA];
        xsm[c*32 + p] = v;
        s += v; s2 += (double)v*(double)v;
    }
    ssum[cg][p] = s; ssq[cg][p] = s2;
    __syncthreads();
    if (tid < 32) {
        double ts = 0.0, tq = 0.0;
        #pragma unroll
        for (int g = 0; g < 8; g++) { ts += ssum[g][tid]; tq += ssq[g][tid]; }
        double m   = ts / 256.0;
        double var = tq / 256.0 - m*m;
        mbuf[tid] = (float)m;
        rbuf[tid] = (float)(1.0 / sqrt(var + 1e-5));
    }
    __syncthreads();
    float m = mbuf[p], r = rbuf[p];
    float* xo_b = xb_out + (size_t)b*CDIM*SPA + hh*WDIM + p;
    float* xo_s = xs_out + (size_t)b*CDIM*SPA + hh*WDIM + p;
    #pragma unroll
    for (int j = 0; j < 32; j++) {
        int c = cg*32 + j;
        float t = (xsm[c*32 + p] - m) * r * gma[c] + bta[c];
        float big = __uint_as_float(f2tf(t));
        xo_b[(size_t)c*SPA] = big;
        xo_s[(size_t)c*SPA] = __uint_as_float(f2tf(t - big));
    }
}

// ------------------------- tf32 GEMM: 128x128x32, 4 warps, 64x64 warp tile --
// out[b, oc_base+m, n] = bias[m] + sum_c wt[c][m] * X[b,c,n] (+res).
// X = concat(in1 [logical 0,ic1log) with optional &255 wrap], in2 rest).
// flags: 1 = per-32-row l2 normalize epilogue; 2 = accumulate (b,m) stats.
// PRER: X values already tf32-rounded (skip cvt).
#define CP16(dst, src) asm volatile("cp.async.ca.shared.global [%0], [%1], 16;\n" \
    :: "r"(dst), "l"(src))

template<int PRER>
__global__ void __launch_bounds__(128)
gemm_tf32(const float* __restrict__ in1, const float* __restrict__ in2,
          int ic1log, int ic1p, int ic_total, int wrap,
          const float* __restrict__ wt, int oc_w,
          const float* __restrict__ bias,
          const float* __restrict__ res, float* __restrict__ out,
          int oc_out, int oc_base, int flags,
          float* __restrict__ s1g, float* __restrict__ s2g) {
    extern __shared__ float sm[];
    float* Wt0 = sm;              // [2][32*128]
    float* Xt0 = sm + 8192;       // [2][32*128]

    int oc0 = blockIdx.x * 128;
    int p0  = blockIdx.y * 128;
    int b   = blockIdx.z;
    int tid = threadIdx.x;
    int lane = tid & 31, wid = tid >> 5;
    int gid = lane >> 2, tig = lane & 3;
    int warpm0 = (wid & 1) * 64;
    int warpn0 = (wid >> 1) * 64;
    int swz = tig * 8;

    const float* in1b = in1 + (size_t)b*ic1p*SPA + p0;
    const float* in2b = in2 ? (in2 + (size_t)b*(ic_total - ic1log)*SPA + p0)
                            : (const float*)0;
    const float* wbase = wt + oc0 + lane*4;

    float acc[4][8][4];
    #pragma unroll
    for (int mt = 0; mt < 4; mt++)
        #pragma unroll
        for (int nt = 0; nt < 8; nt++)
            #pragma unroll
            for (int q = 0; q < 4; q++) acc[mt][nt][q] = 0.f;

    int ntiles = ic_total >> 5;

    #define COPY_TILE(K0, S) do {                                              \
        float* Wd = Wt0 + (S)*4096;                                           \
        float* Xd = Xt0 + (S)*4096;                                           \
        _Pragma("unroll")                                                      \
        for (int r = 0; r < 8; r++) {                                          \
            int k = r*4 + wid;                                                 \
            int col = (lane*4) ^ ((k & 3)*8);                                  \
            const float* wsrc = wbase + (size_t)((K0) + k)*oc_w;               \
            CP16((unsigned)__cvta_generic_to_shared(Wd + k*128 + col), wsrc);  \
            int c = (K0) + k;                                                  \
            const float* xsrc;                                                 \
            if (c < ic1log) {                                                  \
                int ce = wrap ? (c & 255) : c;                                 \
                xsrc = in1b + (size_t)ce*SPA;                                  \
            } else {                                                           \
                xsrc = in2b + (size_t)(c - ic1log)*SPA;                        \
            }                                                                  \
            CP16((unsigned)__cvta_generic_to_shared(Xd + k*128 + col),         \
                 xsrc + lane*4);                                               \
        }                                                                      \
    } while (0)

    COPY_TILE(0, 0);
    asm volatile("cp.async.commit_group;\n");

    #pragma unroll 1
    for (int t = 0; t < ntiles; t++) {
        if (t + 1 < ntiles) {
            COPY_TILE((t+1)*32, (t+1)&1);
            asm volatile("cp.async.commit_group;\n");
            asm volatile("cp.async.wait_group 1;\n");
        } else {
            asm volatile("cp.async.wait_group 0;\n");
        }
        __syncthreads();
        const float* Wk = Wt0 + (t&1)*4096;
        const float* Xk = Xt0 + (t&1)*4096;
        #pragma unroll
        for (int step = 0; step < 4; step++) {
            int r0 = step*8 + tig, r1 = r0 + 4;
            uint32_t a[4][4], bf[8][2];
            #pragma unroll
            for (int mt = 0; mt < 4; mt++) {
                int m = warpm0 + mt*16 + gid;
                a[mt][0] = __float_as_uint(Wk[r0*128 + ( m      ^ swz)]);
                a[mt][1] = __float_as_uint(Wk[r0*128 + ((m + 8) ^ swz)]);
                a[mt][2] = __float_as_uint(Wk[r1*128 + ( m      ^ swz)]);
                a[mt][3] = __float_as_uint(Wk[r1*128 + ((m + 8) ^ swz)]);
            }
            #pragma unroll
            for (int nt = 0; nt < 8; nt++) {
                int n = warpn0 + nt*8 + gid;
                if (PRER) {
                    bf[nt][0] = __float_as_uint(Xk[r0*128 + (n ^ swz)]);
                    bf[nt][1] = __float_as_uint(Xk[r1*128 + (n ^ swz)]);
                } else {
                    bf[nt][0] = f2tf(Xk[r0*128 + (n ^ swz)]);
                    bf[nt][1] = f2tf(Xk[r1*128 + (n ^ swz)]);
                }
            }
            #pragma unroll
            for (int mt = 0; mt < 4; mt++)
                #pragma unroll
                for (int nt = 0; nt < 8; nt++) {
                    asm volatile(
                        "mma.sync.aligned.m16n8k8.row.col.f32.tf32.tf32.f32 "
                        "{%0,%1,%2,%3}, {%4,%5,%6,%7}, {%8,%9}, {%0,%1,%2,%3};"
                        : "+f"(acc[mt][nt][0]), "+f"(acc[mt][nt][1]),
                          "+f"(acc[mt][nt][2]), "+f"(acc[mt][nt][3])
                        : "r"(a[mt][0]), "r"(a[mt][1]), "r"(a[mt][2]), "r"(a[mt][3]),
                          "r"(bf[nt][0]), "r"(bf[nt][1]));
                }
        }
        __syncthreads();
    }

    // optional fused l2 norm over 32-wide spatial rows (q/k)
    if (flags & 1) {
        #pragma unroll
        for (int mt = 0; mt < 4; mt++)
            #pragma unroll
            for (int rr = 0; rr < 2; rr++)
                #pragma unroll
                for (int g = 0; g < 2; g++) {   // nt groups {0..3},{4..7} = rows of 32
                    float ss = 0.f;
                    #pragma unroll
                    for (int q = 0; q < 4; q++) {
                        float a0 = acc[mt][g*4+q][rr*2+0];
                        float a1 = acc[mt][g*4+q][rr*2+1];
                        ss += a0*a0 + a1*a1;
                    }
                    ss += __shfl_xor_sync(0xffffffffu, ss, 1);
                    ss += __shfl_xor_sync(0xffffffffu, ss, 2);
                    float inv = 1.f / fmaxf(sqrtf(ss), 1e-12f);
                    #pragma unroll
                    for (int q = 0; q < 4; q++) {
                        acc[mt][g*4+q][rr*2+0] *= inv;
                        acc[mt][g*4+q][rr*2+1] *= inv;
                    }
                }
    }

    // epilogue
    #pragma unroll
    for (int mt = 0; mt < 4; mt++) {
        #pragma unroll
        for (int rr = 0; rr < 2; rr++) {
            int mloc = oc0 + warpm0 + mt*16 + rr*8 + gid;
            float bi = bias ? bias[mloc] : 0.f;
            size_t ob = ((size_t)b*oc_out + oc_base + mloc)*SPA + p0 + warpn0 + tig*2;
            float psum = 0.f, psq = 0.f;
            #pragma unroll
            for (int nt = 0; nt < 8; nt++) {
                float2 v;
                v.x = acc[mt][nt][rr*2 + 0] + bi;
                v.y = acc[mt][nt][rr*2 + 1] + bi;
                if (res) {
                    float2 rv = *(const float2*)(res + ob + nt*8);
                    v.x += rv.x; v.y += rv.y;
                }
                *(float2*)(out + ob + nt*8) = v;
                if (flags & 2) { psum += v.x + v.y; psq += v.x*v.x + v.y*v.y; }
            }
            if (flags & 2) {
                psum += __shfl_xor_sync(0xffffffffu, psum, 1);
                psum += __shfl_xor_sync(0xffffffffu, psum, 2);
                psq  += __shfl_xor_sync(0xffffffffu, psq, 1);
                psq  += __shfl_xor_sync(0xffffffffu, psq, 2);
                if (tig == 0) {
                    atomicAdd(&s1g[b*oc_out + mloc], psum);
                    atomicAdd(&s2g[b*oc_out + mloc], psq);
                }
            }
        }
    }
}

// ------------------------- q_probe[bh][w] = sum_{dh,hh} qn -------------------
__global__ void probe_kernel(const float* __restrict__ qkv, float* __restrict__ probe) {
    int bh = blockIdx.x;
    int b = bh >> 3, head = bh & 7;
    int tid = threadIdx.x;
    int w = tid & 31, grp = tid >> 5;
    const float* qb = qkv + ((size_t)b*768 + head*32)*SPA;
    float s = 0.f;
    for (int idx = grp; idx < 32*256; idx += 8)
        s += qb[(size_t)idx*32 + w];
    __shared__ float red[8][32];
    red[grp][w] = s;
    __syncthreads();
    if (tid < 32) {
        float t = 0.f;
        #pragma unroll
        for (int g = 0; g < 8; g++) t += red[g][tid];
        probe[bh*32 + tid] = t;
    }
}

// ------------------------- top-k selection + gather -------------------------
__global__ void select_kernel(const float* __restrict__ qkv,
                              const float* __restrict__ probe,
                              float* __restrict__ k2, float* __restrict__ v2) {
    int bh = blockIdx.x;
    int b = bh >> 3, head = bh & 7;
    int tid = threadIdx.x;
    int w = tid & 31;
    const float* kb = qkv + ((size_t)b*768 + 256 + head*32)*SPA;
    const float* vb = qkv + ((size_t)b*768 + 512 + head*32)*SPA;
    __shared__ float pr[32];
    __shared__ float kh[32][32];
    __shared__ float sh[32];
    __shared__ int   sel_dh[8];
    __shared__ float ks2[256][33];
    __shared__ float sw[256];
    __shared__ int   sel_hh[8];
    if (tid < 32) pr[tid] = probe[bh*32 + tid];
    for (int dh = tid >> 5; dh < 32; dh += 8) {
        float s = 0.f;
        for (int hh = 0; hh < 256; hh++)
            s += kb[(size_t)dh*8192 + hh*32 + w];
        kh[dh][w] = s;
    }
    __syncthreads();
    if (tid < 32) {
        float s = 0.f;
        #pragma unroll
        for (int w2 = 0; w2 < 32; w2++) s += pr[w2] * kh[tid][w2];
        sh[tid] = s;
    }
    __syncthreads();
    if (tid == 0) {
        unsigned used = 0u;
        for (int j = 0; j < 8; j++) {
            int best = -1; float bv = -FLT_MAX;
            for (int d2 = 0; d2 < 32; d2++) {
                if ((used >> d2) & 1u) continue;
                if (best < 0 || sh[d2] > bv) { best = d2; bv = sh[d2]; }
            }
            used |= 1u << best;
            sel_dh[j] = best;
        }
    }
    __syncthreads();
    for (int hh = tid >> 5; hh < 256; hh += 8) {
        float s = 0.f;
        #pragma unroll
        for (int j = 0; j < 8; j++)
            s += kb[(size_t)sel_dh[j]*8192 + hh*32 + w];
        ks2[hh][w] = s;
    }
    __syncthreads();
    {
        float s = 0.f;
        #pragma unroll
        for (int w2 = 0; w2 < 32; w2++) s += pr[w2] * ks2[tid][w2];
        sw[tid] = s;
    }
    __syncthreads();
    if (tid == 0) {
        unsigned um[8] = {0,0,0,0,0,0,0,0};
        for (int j = 0; j < 8; j++) {
            int best = -1; float bv = -FLT_MAX;
            for (int h2 = 0; h2 < 256; h2++) {
                if ((um[h2 >> 5] >> (h2 & 31)) & 1u) continue;
                if (best < 0 || sw[h2] > bv) { best = h2; bv = sw[h2]; }
            }
            um[best >> 5] |= 1u << (best & 31);
            sel_hh[j] = best;
        }
    }
    __syncthreads();
    for (int j = tid >> 5; j < 64; j += 8) {
        int jd = j >> 3, jw = j & 7;
        size_t src = (size_t)sel_dh[jd]*8192 + sel_hh[jw]*32 + w;
        k2[(size_t)(bh*64 + j)*32 + w] = kb[src];
        v2[(size_t)(bh*64 + j)*32 + w] = vb[src];
    }
}

// ------------------------- attention (64 keys) + transpose write ------------
__global__ void attn_kernel(const float* __restrict__ qkv,
                            const float* __restrict__ k2,
                            const float* __restrict__ v2,
                            float* __restrict__ o_r) {
    __shared__ float k2s[64*33];
    __shared__ float v2s[64*33];
    __shared__ float os[32*129];
    int bh = blockIdx.y;
    int b = bh >> 3, head = bh & 7;
    int i0 = blockIdx.x * 128;
    int tid = threadIdx.x;
    int lane = tid & 31, wid = tid >> 5;
    #pragma unroll
    for (int r = 0; r < 8; r++) {
        int jj = wid + r*8;
        k2s[jj*33 + lane] = k2[(size_t)(bh*64 + jj)*32 + lane];
        v2s[jj*33 + lane] = v2[(size_t)(bh*64 + jj)*32 + lane];
    }
    __syncthreads();
    const float* qb = qkv + ((size_t)b*768 + head*32)*SPA;
    for (int it = 0; it < 16; it++) {
        int li = wid*16 + it;
        int i = i0 + li;
        float qv = qb[(size_t)i*32 + lane];
        float s0 = 0.f, s1 = 0.f;
        #pragma unroll
        for (int d = 0; d < 32; d++) {
            float qd = __shfl_sync(0xffffffffu, qv, d);
            s0 = fmaf(qd, k2s[lane*33 + d], s0);
            s1 = fmaf(qd, k2s[(lane+32)*33 + d], s1);
        }
        float mx = fmaxf(s0, s1);
        #pragma unroll
        for (int o = 16; o; o >>= 1) mx = fmaxf(mx, __shfl_xor_sync(0xffffffffu, mx, o));
        float p0 = expf(s0 - mx), p1 = expf(s1 - mx);
        float ssm = p0 + p1;
        #pragma unroll
        for (int o = 16; o; o >>= 1) ssm += __shfl_xor_sync(0xffffffffu, ssm, o);
        float inv = 1.f / ssm;
        float ov = 0.f;
        #pragma unroll
        for (int j = 0; j < 32; j++) {
            float pa = __shfl_sync(0xffffffffu, p0, j);
            float pb = __shfl_sync(0xffffffffu, p1, j);
            ov = fmaf(pa, v2s[j*33 + lane], ov);
            ov = fmaf(pb, v2s[(j+32)*33 + lane], ov);
        }
        os[lane*129 + li] = ov * inv;
    }
    __syncthreads();
    #pragma unroll
    for (int dblk = 0; dblk < 4; dblk++) {
        int d = dblk*8 + wid;
        float* ob = o_r + ((size_t)b*256 + head*32 + d)*SPA + i0;
        #pragma unroll
        for (int cs = 0; cs < 4; cs++)
            ob[cs*32 + lane] = os[d*129 + cs*32 + lane];
    }
}

// ------------------------- depthwise 3x3 (SAME), plain ----------------------
__global__ void dwconv3_kernel(const float* __restrict__ in, const float* __restrict__ w,
                               const float* __restrict__ bias, float* __restrict__ out) {
    int b = blockIdx.z;
    int c = blockIdx.y;
    int C = gridDim.y;
    int hh = blockIdx.x*8 + (threadIdx.x >> 5);
    int ww = threadIdx.x & 31;
    const float* ib = in + ((size_t)b*C + c)*SPA;
    float s = bias[c];
    #pragma unroll
    for (int dy = 0; dy < 3; dy++) {
        int y = hh + dy - 1;
        if (y < 0 || y >= HDIM) continue;
        #pragma unroll
        for (int dx = 0; dx < 3; dx++) {
            int x2 = ww + dx - 1;
            if (x2 < 0 || x2 >= WDIM) continue;
            s = fmaf(ib[y*WDIM + x2], w[c*9 + dy*3 + dx], s);
        }
    }
    out[((size_t)b*C + c)*SPA + hh*WDIM + ww] = s;
}

// ---------- depthwise 3x3 over gelu(inorm(raw)) using precomputed stats -----
__global__ void dwconv3_gn_kernel(const float* __restrict__ in, const float* __restrict__ w,
                                  const float* __restrict__ bias,
                                  const float* __restrict__ s1, const float* __restrict__ s2,
                                  float* __restrict__ out) {
    __shared__ float tile[10*32];
    int b = blockIdx.z, c = blockIdx.y;
    int C = gridDim.y;
    int bc = b*C + c;
    float m  = s1[bc] * (1.f/8192.f);
    float var = s2[bc] * (1.f/8192.f) - m*m;
    float r = rsqrtf(var + 1e-5f);
    int hh0 = blockIdx.x * 8;
    const float* ib = in + (size_t)bc*SPA;
    for (int i = threadIdx.x; i < 320; i += 256) {
        int row = i >> 5, col = i & 31;
        int y = hh0 + row - 1;
        float v = 0.f;
        if (y >= 0 && y < HDIM) {
            float t = (ib[y*32 + col] - m) * r;
            v = 0.5f * t * (1.f + erff(t * 0.70710678118654752f));
        }
        tile[i] = v;
    }
    __syncthreads();
    int hl = threadIdx.x >> 5, ww = threadIdx.x & 31;
    float s = bias[c];
    #pragma unroll
    for (int dy = 0; dy < 3; dy++) {
        #pragma unroll
        for (int dx = 0; dx < 3; dx++) {
            int x2 = ww + dx - 1;
            if (x2 < 0 || x2 >= WDIM) continue;
            s = fmaf(tile[(hl + dy)*32 + x2], w[c*9 + dy*3 + dx], s);
        }
    }
    out[(size_t)bc*SPA + (hh0 + hl)*32 + ww] = s;
}

// ------------------------- instance norm: mode 0 (plain) --------------------
__global__ void inorm_kernel(const float* __restrict__ in, float* __restrict__ out) {
    size_t base = (size_t)blockIdx.x * SPA;
    int tid = threadIdx.x;
    float v[32];
    double s = 0.0, s2 = 0.0;
    #pragma unroll
    for (int j = 0; j < 32; j++) {
        float t = in[base + j*256 + tid];
        v[j] = t;
        s += t; s2 += (double)t*(double)t;
    }
    __shared__ double rs[8], rq[8];
    __shared__ float mv[2];
    #pragma unroll
    for (int o = 16; o; o >>= 1) {
        s  += __shfl_xor_sync(0xffffffffu, s, o);
        s2 += __shfl_xor_sync(0xffffffffu, s2, o);
    }
    if ((tid & 31) == 0) { rs[tid >> 5] = s; rq[tid >> 5] = s2; }
    __syncthreads();
    if (tid == 0) {
        double ts = 0.0, tq = 0.0;
        #pragma unroll
        for (int g = 0; g < 8; g++) { ts += rs[g]; tq += rq[g]; }
        double m   = ts / (double)SPA;
        double var = tq / (double)SPA - m*m;
        mv[0] = (float)m;
        mv[1] = (float)(1.0 / sqrt(var + 1e-5));
    }
    __syncthreads();
    float m = mv[0], r = mv[1];
    #pragma unroll
    for (int j = 0; j < 32; j++)
        out[base + j*256 + tid] = (v[j] - m) * r;
}

// --------- h2 = gelu(norm_ffraw(add)) + gelu(inorm(in)) ; add = raw ff1 -----
__global__ void inorm_addgn_kernel(const float* __restrict__ in,
                                   const float* __restrict__ addraw,
                                   const float* __restrict__ s1,
                                   const float* __restrict__ s2,
                                   float* __restrict__ out) {
    size_t base = (size_t)blockIdx.x * SPA;
    int tid = threadIdx.x;
    float ma  = s1[blockIdx.x] * (1.f/8192.f);
    float va  = s2[blockIdx.x] * (1.f/8192.f) - ma*ma;
    float ra  = rsqrtf(va + 1e-5f);
    float v[32];
    double s = 0.0, s2l = 0.0;
    #pragma unroll
    for (int j = 0; j < 32; j++) {
        float t = in[base + j*256 + tid];
        v[j] = t;
        s += t; s2l += (double)t*(double)t;
    }
    __shared__ double rs[8], rq[8];
    __shared__ float mv[2];
    #pragma unroll
    for (int o = 16; o; o >>= 1) {
        s   += __shfl_xor_sync(0xffffffffu, s, o);
        s2l += __shfl_xor_sync(0xffffffffu, s2l, o);
    }
    if ((tid & 31) == 0) { rs[tid >> 5] = s; rq[tid >> 5] = s2l; }
    __syncthreads();
    if (tid == 0) {
        double ts = 0.0, tq = 0.0;
        #pragma unroll
        for (int g = 0; g < 8; g++) { ts += rs[g]; tq += rq[g]; }
        double m   = ts / (double)SPA;
        double var = tq / (double)SPA - m*m;
        mv[0] = (float)m;
        mv[1] = (float)(1.0 / sqrt(var + 1e-5));
    }
    __syncthreads();
    float m = mv[0], r = mv[1];
    #pragma unroll
    for (int j = 0; j < 32; j++) {
        float t = (v[j] - m) * r;
        t = 0.5f * t * (1.f + erff(t * 0.70710678118654752f));
        float a = (addraw[base + j*256 + tid] - ma) * ra;
        a = 0.5f * a * (1.f + erff(a * 0.70710678118654752f));
        out[base + j*256 + tid] = t + a;
    }
}

// ------------------------- host orchestration -------------------------------
extern "C" void kernel_launch(void* const* d_in, const int* in_sizes, int n_in,
                              void* d_out, int out_size) {
    (void)in_sizes; (void)n_in; (void)out_size;
    const float* x      = (const float*)d_in[0];
    const float* cln_g  = (const float*)d_in[1];
    const float* cln_b  = (const float*)d_in[2];
    const float* w_qkv  = (const float*)d_in[3];
    const float* w_out  = (const float*)d_in[4];
    const float* b_out  = (const float*)d_in[5];
    const float* w_dw   = (const float*)d_in[6];
    const float* b_dw   = (const float*)d_in[7];
    const float* w_comb = (const float*)d_in[8];
    const float* b_comb = (const float*)d_in[9];
    const float* w_ff1  = (const float*)d_in[10];
    const float* b_ff1  = (const float*)d_in[11];
    const float* w_ffdw = (const float*)d_in[12];
    const float* b_ffdw = (const float*)d_in[13];
    const float* w_ff2  = (const float*)d_in[14];
    const float* b_ff2  = (const float*)d_in[15];
    float* out = (float*)d_out;

    float *p_xn, *p_xs, *p_qkv, *p_or, *p_attn, *p_conv, *p_comb, *p_ff1, *p_ffdw, *p_ff2;
    float *p_probe, *p_k2, *p_v2, *p_wt, *p_s1, *p_s2;
    cudaGetSymbolAddress((void**)&p_xn,   g_xn);
    cudaGetSymbolAddress((void**)&p_xs,   g_xs);
    cudaGetSymbolAddress((void**)&p_qkv,  g_qkv);
    cudaGetSymbolAddress((void**)&p_or,   g_or);
    cudaGetSymbolAddress((void**)&p_attn, g_attn);
    cudaGetSymbolAddress((void**)&p_conv, g_conv);
    cudaGetSymbolAddress((void**)&p_comb, g_comb);
    cudaGetSymbolAddress((void**)&p_ff1,  g_ff1);
    cudaGetSymbolAddress((void**)&p_ffdw, g_ffdw);
    cudaGetSymbolAddress((void**)&p_ff2,  g_ff2);
    cudaGetSymbolAddress((void**)&p_probe,g_probe);
    cudaGetSymbolAddress((void**)&p_k2,   g_k2);
    cudaGetSymbolAddress((void**)&p_v2,   g_v2);
    cudaGetSymbolAddress((void**)&p_wt,   g_wt);
    cudaGetSymbolAddress((void**)&p_s1,   g_s1);
    cudaGetSymbolAddress((void**)&p_s2,   g_s2);

    static bool attr_set = false;
    if (!attr_set) {
        cudaFuncSetAttribute(gemm_tf32<0>,
            cudaFuncAttributeMaxDynamicSharedMemorySize, 65536);
        cudaFuncSetAttribute(gemm_tf32<1>,
            cudaFuncAttributeMaxDynamicSharedMemorySize, 65536);
        attr_set = true;
    }
    const int GSM = 65536;

    // 0) weight transposes (+ tf32 rounding)
    transpose_kernel<<<dim3(8, 8),  256>>>(w_out,  p_wt + WT_OUT,  256, 256);
    transpose_kernel<<<dim3(16, 8), 256>>>(w_comb, p_wt + WT_COMB, 256, 512);
    transpose_kernel<<<dim3(8, 32), 256>>>(w_ff1,  p_wt + WT_FF1,  1024, 256);
    transpose_kernel<<<dim3(32, 8), 256>>>(w_ff2,  p_wt + WT_FF2,  256, 1024);
    transpose_split_qk<<<dim3(8, 16), 256>>>(w_qkv, p_wt + WT_QK);
    transpose_kernel<<<dim3(8, 8),  256>>>(w_qkv + 512*256, p_wt + WT_V, 256, 256);
    zero_stats<<<32, 256>>>(p_s1, p_s2);

    // 1) channel LN -> tf32 split (xb in p_xn, xs in p_xs)
    chan_ln_kernel<<<dim3(HDIM, BATCH), 256>>>(x, cln_g, cln_b, p_xn, p_xs);

    // 2a) q,k = exact tf32 split GEMM (K=768, [Wb;Ws;Wb] x [xb;xb;xs]) + fused l2norm
    gemm_tf32<1><<<dim3(4, 64, 8), 128, GSM>>>(p_xn, p_xs, 512, 256, 768, 1,
        p_wt + WT_QK, 512, nullptr, nullptr, p_qkv, 768, 0, /*flags=*/1, nullptr, nullptr);
    // 2b) v = single tf32 GEMM (K=256)
    gemm_tf32<1><<<dim3(2, 64, 8), 128, GSM>>>(p_xn, nullptr, 256, 256, 256, 0,
        p_wt + WT_V, 256, nullptr, nullptr, p_qkv, 768, 512, 0, nullptr, nullptr);

    // 3) q_probe
    probe_kernel<<<NBH, 256>>>(p_qkv, p_probe);
    // 4) top-k selection + gather
    select_kernel<<<NBH, 256>>>(p_qkv, p_probe, p_k2, p_v2);
    // 5) attention + transpose
    attn_kernel<<<dim3(64, NBH), 256>>>(p_qkv, p_k2, p_v2, p_or);
    // 6) attn_branch = conv1x1(o_r, w_out, b_out)
    gemm_tf32<0><<<dim3(2, 64, 8), 128, GSM>>>(p_or, nullptr, 256, 256, 256, 0,
        p_wt + WT_OUT, 256, b_out, nullptr, p_attn, 256, 0, 0, nullptr, nullptr);
    // 7) conv_branch = dwconv3(x)
    dwconv3_kernel<<<dim3(32, 256, 8), 256>>>(x, w_dw, b_dw, p_conv);
    // 8) comb = conv1x1(concat(attn, conv)) + x
    gemm_tf32<0><<<dim3(2, 64, 8), 128, GSM>>>(p_attn, p_conv, 256, 256, 512, 0,
        p_wt + WT_COMB, 256, b_comb, x, p_comb, 256, 0, 0, nullptr, nullptr);
    // 9) ff1 raw (+ fused per-(b,c) stats via atomics)
    gemm_tf32<0><<<dim3(8, 64, 8), 128, GSM>>>(p_comb, nullptr, 256, 256, 256, 0,
        p_wt + WT_FF1, 1024, b_ff1, nullptr, p_ff1, 1024, 0, /*flags=*/2, p_s1, p_s2);
    // 10) ffdw = dwconv3(gelu(inorm(ff1)))  -- transform fused on tile load
    dwconv3_gn_kernel<<<dim3(32, 1024, 8), 256>>>(p_ff1, w_ffdw, b_ffdw, p_s1, p_s2, p_ffdw);
    // 11) h2 = gelu(inorm_ff1(ff1)) + gelu(inorm(ffdw))
    inorm_addgn_kernel<<<BATCH*FFI, 256>>>(p_ffdw, p_ff1, p_s1, p_s2, p_ffdw);
    // 12) ff2
    gemm_tf32<0><<<dim3(2, 64, 8), 128, GSM>>>(p_ffdw, nullptr, 1024, 1024, 1024, 0,
        p_wt + WT_FF2, 256, b_ff2, nullptr, p_ff2, 256, 0, 0, nullptr, nullptr);
    // 13) out = inorm(ff2)
    inorm_kernel<<<BATCH*CDIM, 256>>>(p_ff2, out);
}

// round 16
// speedup vs baseline: 1.1848x; 1.0085x over previous
#include <cuda_runtime.h>
#include <math.h>
#include <float.h>
#include <stdint.h>

#define BATCH 8
#define CDIM  256
#define HDIM  256
#define WDIM  32
#define SPA   8192      // HDIM*WDIM
#define FFI   1024
#define NBH   64        // BATCH*HEADS

// ------------------------- scratch (device globals) -------------------------
__device__ float g_xn  [BATCH*CDIM*SPA];   // tf32-rounded "big" part of xn
__device__ float g_xs  [BATCH*CDIM*SPA];   // tf32-rounded "small" residual
__device__ float g_qkv [BATCH*3*CDIM*SPA];
__device__ float g_or  [BATCH*CDIM*SPA];
__device__ float g_attn[BATCH*CDIM*SPA];
__device__ float g_conv[BATCH*CDIM*SPA];
__device__ float g_comb[BATCH*CDIM*SPA];
__device__ float g_ff1 [BATCH*FFI*SPA];
__device__ float g_ffdw[BATCH*FFI*SPA];
__device__ float g_ff2 [BATCH*CDIM*SPA];
__device__ float g_probe[NBH*32];
__device__ float g_k2 [NBH*64*32];
__device__ float g_v2 [NBH*64*32];
__device__ float g_wt [1310720];   // transposed (K-major), tf32-rounded weights
__device__ float g_s1 [BATCH*FFI]; // ff1 per-(b,c) sum
__device__ float g_s2 [BATCH*FFI]; // ff1 per-(b,c) sumsq

// wt offsets (floats)
#define WT_OUT  0          // 256 rows x 256
#define WT_COMB 65536      // 512 x 256
#define WT_FF1  196608     // 256 x 1024
#define WT_FF2  458752     // 1024 x 256
#define WT_QK   720896     // 768 x 512  ([Wb; Ws; Wb] rows, qk cols only)
#define WT_V    1114112    // 256 x 256

__device__ __forceinline__ uint32_t f2tf(float f) {
    uint32_t r;
    asm("cvt.rna.tf32.f32 %0, %1;" : "=r"(r) : "f"(f));
    return r;
}
__device__ __forceinline__ float rtf(float f) { return __uint_as_float(f2tf(f)); }

// ------------------------- weight transpose (+ tf32 round) ------------------
__global__ void transpose_kernel(const float* __restrict__ w, float* __restrict__ wt,
                                 int M, int K) {
    __shared__ float t[32][33];
    int k0 = blockIdx.x*32, m0 = blockIdx.y*32;
    int tx = threadIdx.x & 31, ty = threadIdx.x >> 5;   // 32 x 8
    #pragma unroll
    for (int r = 0; r < 4; r++)
        t[ty + r*8][tx] = w[(size_t)(m0 + ty + r*8)*K + k0 + tx];
    __syncthreads();
    #pragma unroll
    for (int r = 0; r < 4; r++)
        wt[(size_t)(k0 + ty + r*8)*M + m0 + tx] = rtf(t[tx][ty + r*8]);
}

// 4 weight transposes fused into one launch (1D grid, segment decode)
__global__ void transpose4_kernel(const float* __restrict__ w_out,
                                  const float* __restrict__ w_comb,
                                  const float* __restrict__ w_ff1,
                                  const float* __restrict__ w_ff2,
                                  float* __restrict__ wt) {
    __shared__ float t[32][33];
    int idx = blockIdx.x;
    const float* w; float* dst; int M, K, kb, local;
    if (idx < 64)        { w = w_out;  dst = wt + WT_OUT;  M = 256;  K = 256;  kb = 8;  local = idx; }
    else if (idx < 192)  { w = w_comb; dst = wt + WT_COMB; M = 256;  K = 512;  kb = 16; local = idx - 64; }
    else if (idx < 448)  { w = w_ff1;  dst = wt + WT_FF1;  M = 1024; K = 256;  kb = 8;  local = idx - 192; }
    else                 { w = w_ff2;  dst = wt + WT_FF2;  M = 256;  K = 1024; kb = 32; local = idx - 448; }
    int k0 = (local % kb)*32, m0 = (local / kb)*32;
    int tx = threadIdx.x & 31, ty = threadIdx.x >> 5;
    #pragma unroll
    for (int r = 0; r < 4; r++)
        t[ty + r*8][tx] = w[(size_t)(m0 + ty + r*8)*K + k0 + tx];
    __syncthreads();
    #pragma unroll
    for (int r = 0; r < 4; r++)
        dst[(size_t)(k0 + ty + r*8)*M + m0 + tx] = rtf(t[tx][ty + r*8]);
}

// qk part of qkv weight: rows m<512 -> wq [768 K-rows][512 cols]:
// rows 0-255 = Wb^T, 256-511 = Ws^T, 512-767 = Wb^T.
__global__ void transpose_split_qk(const float* __restrict__ w, float* __restrict__ wq) {
    __shared__ float t[32][33];
    int k0 = blockIdx.x*32, m0 = blockIdx.y*32;   // k over 256, m over 512
    int tx = threadIdx.x & 31, ty = threadIdx.x >> 5;
    #pragma unroll
    for (int r = 0; r < 4; r++)
        t[ty + r*8][tx] = w[(size_t)(m0 + ty + r*8)*256 + k0 + tx];
    __syncthreads();
    #pragma unroll
    for (int r = 0; r < 4; r++) {
        int k = k0 + ty + r*8;
        int m = m0 + tx;
        float v = t[tx][ty + r*8];
        float big = rtf(v);
        float sml = rtf(v - big);
        wq[(size_t)k*512 + m]         = big;
        wq[(size_t)(256 + k)*512 + m] = sml;
        wq[(size_t)(512 + k)*512 + m] = big;
    }
}

__global__ void zero_stats(float* __restrict__ s1, float* __restrict__ s2) {
    int i = blockIdx.x*256 + threadIdx.x;
    if (i < BATCH*FFI) { s1[i] = 0.f; s2[i] = 0.f; }
}

// ------------------------- channel LayerNorm (axis=C) + tf32 split ----------
__global__ void chan_ln_kernel(const float* __restrict__ x,
                               const float* __restrict__ gma,
                               const float* __restrict__ bta,
                               float* __restrict__ xb_out,
                               float* __restrict__ xs_out) {
    __shared__ float  xsm[CDIM*32];
    __shared__ double ssum[8][32];
    __shared__ double ssq [8][32];
    __shared__ float  mbuf[32], rbuf[32];
    int b = blockIdx.y, hh = blockIdx.x;
    int tid = threadIdx.x;
    int cg = tid >> 5, p = tid & 31;
    const float* xbp = x + (size_t)b*CDIM*SPA + hh*WDIM + p;
    double s = 0.0, s2 = 0.0;
    #pragma unroll
    for (int j = 0; j < 32; j++) {
        int c = cg*32 + j;
        float v = xbp[(size_t)c*SPA];
        xsm[c*32 + p] = v;
        s += v; s2 += (double)v*(double)v;
    }
    ssum[cg][p] = s; ssq[cg][p] = s2;
    __syncthreads();
    if (tid < 32) {
        double ts = 0.0, tq = 0.0;
        #pragma unroll
        for (int g = 0; g < 8; g++) { ts += ssum[g][tid]; tq += ssq[g][tid]; }
        double m   = ts / 256.0;
        double var = tq / 256.0 - m*m;
        mbuf[tid] = (float)m;
        rbuf[tid] = (float)(1.0 / sqrt(var + 1e-5));
    }
    __syncthreads();
    float m = mbuf[p], r = rbuf[p];
    float* xo_b = xb_out + (size_t)b*CDIM*SPA + hh*WDIM + p;
    float* xo_s = xs_out + (size_t)b*CDIM*SPA + hh*WDIM + p;
    #pragma unroll
    for (int j = 0; j < 32; j++) {
        int c = cg*32 + j;
        float t = (xsm[c*32 + p] - m) * r * gma[c] + bta[c];
        float big = rtf(t);
        xo_b[(size_t)c*SPA] = big;
        xo_s[(size_t)c*SPA] = rtf(t - big);
    }
}

// ------------------------- tf32 GEMM: 128x128x32, 4 warps, 64x64 warp tile --
// out[b, oc_base+m, n] = bias[m] + sum_c wt[c][m] * X[b,c,n] (+res).
// ALL inputs pre-rounded to tf32 (no in-loop cvt).
// flags: 1 = per-32-row l2 normalize; 2 = (b,m) stats atomics; 4 = round output.
#define CP16(dst, src) asm volatile("cp.async.ca.shared.global [%0], [%1], 16;\n" \
    :: "r"(dst), "l"(src))

__global__ void __launch_bounds__(128)
gemm_tf32(const float* __restrict__ in1, const float* __restrict__ in2,
          int ic1log, int ic1p, int ic_total, int wrap,
          const float* __restrict__ wt, int oc_w,
          const float* __restrict__ bias,
          const float* __restrict__ res, float* __restrict__ out,
          int oc_out, int oc_base, int flags,
          float* __restrict__ s1g, float* __restrict__ s2g) {
    extern __shared__ float sm[];
    float* Wt0 = sm;              // [2][32*128]
    float* Xt0 = sm + 8192;       // [2][32*128]

    int oc0 = blockIdx.x * 128;
    int p0  = blockIdx.y * 128;
    int b   = blockIdx.z;
    int tid = threadIdx.x;
    int lane = tid & 31, wid = tid >> 5;
    int gid = lane >> 2, tig = lane & 3;
    int warpm0 = (wid & 1) * 64;
    int warpn0 = (wid >> 1) * 64;
    int swz = tig * 8;

    const float* in1b = in1 + (size_t)b*ic1p*SPA + p0;
    const float* in2b = in2 ? (in2 + (size_t)b*(ic_total - ic1log)*SPA + p0)
                            : (const float*)0;
    const float* wbase = wt + oc0 + lane*4;

    float acc[4][8][4];
    #pragma unroll
    for (int mt = 0; mt < 4; mt++)
        #pragma unroll
        for (int nt = 0; nt < 8; nt++)
            #pragma unroll
            for (int q = 0; q < 4; q++) acc[mt][nt][q] = 0.f;

    int ntiles = ic_total >> 5;

    #define COPY_TILE(K0, S) do {                                              \
        float* Wd = Wt0 + (S)*4096;                                           \
        float* Xd = Xt0 + (S)*4096;                                           \
        _Pragma("unroll")                                                      \
        for (int r = 0; r < 8; r++) {                                          \
            int k = r*4 + wid;                                                 \
            int col = (lane*4) ^ ((k & 3)*8);                                  \
            const float* wsrc = wbase + (size_t)((K0) + k)*oc_w;               \
            CP16((unsigned)__cvta_generic_to_shared(Wd + k*128 + col), wsrc);  \
            int c = (K0) + k;                                                  \
            const float* xsrc;                                                 \
            if (c < ic1log) {                                                  \
                int ce = wrap ? (c & 255) : c;                                 \
                xsrc = in1b + (size_t)ce*SPA;                                  \
            } else {                                                           \
                xsrc = in2b + (size_t)(c - ic1log)*SPA;                        \
            }                                                                  \
            CP16((unsigned)__cvta_generic_to_shared(Xd + k*128 + col),         \
                 xsrc + lane*4);                                               \
        }                                                                      \
    } while (0)

    COPY_TILE(0, 0);
    asm volatile("cp.async.commit_group;\n");

    #pragma unroll 1
    for (int t = 0; t < ntiles; t++) {
        if (t + 1 < ntiles) {
            COPY_TILE((t+1)*32, (t+1)&1);
            asm volatile("cp.async.commit_group;\n");
            asm volatile("cp.async.wait_group 1;\n");
        } else {
            asm volatile("cp.async.wait_group 0;\n");
        }
        __syncthreads();
        const float* Wk = Wt0 + (t&1)*4096;
        const float* Xk = Xt0 + (t&1)*4096;
        #pragma unroll
        for (int step = 0; step < 4; step++) {
            int r0 = step*8 + tig, r1 = r0 + 4;
            uint32_t a[4][4], bf[8][2];
            #pragma unroll
            for (int mt = 0; mt < 4; mt++) {
                int m = warpm0 + mt*16 + gid;
                a[mt][0] = __float_as_uint(Wk[r0*128 + ( m      ^ swz)]);
                a[mt][1] = __float_as_uint(Wk[r0*128 + ((m + 8) ^ swz)]);
                a[mt][2] = __float_as_uint(Wk[r1*128 + ( m      ^ swz)]);
                a[mt][3] = __float_as_uint(Wk[r1*128 + ((m + 8) ^ swz)]);
            }
            #pragma unroll
            for (int nt = 0; nt < 8; nt++) {
                int n = warpn0 + nt*8 + gid;
                bf[nt][0] = __float_as_uint(Xk[r0*128 + (n ^ swz)]);
                bf[nt][1] = __float_as_uint(Xk[r1*128 + (n ^ swz)]);
            }
            #pragma unroll
            for (int mt = 0; mt < 4; mt++)
                #pragma unroll
                for (int nt = 0; nt < 8; nt++) {
                    asm volatile(
                        "mma.sync.aligned.m16n8k8.row.col.f32.tf32.tf32.f32 "
                        "{%0,%1,%2,%3}, {%4,%5,%6,%7}, {%8,%9}, {%0,%1,%2,%3};"
                        : "+f"(acc[mt][nt][0]), "+f"(acc[mt][nt][1]),
                          "+f"(acc[mt][nt][2]), "+f"(acc[mt][nt][3])
                        : "r"(a[mt][0]), "r"(a[mt][1]), "r"(a[mt][2]), "r"(a[mt][3]),
                          "r"(bf[nt][0]), "r"(bf[nt][1]));
                }
        }
        __syncthreads();
    }

    // optional fused l2 norm over 32-wide spatial rows (q/k)
    if (flags & 1) {
        #pragma unroll
        for (int mt = 0; mt < 4; mt++)
            #pragma unroll
            for (int rr = 0; rr < 2; rr++)
                #pragma unroll
                for (int g = 0; g < 2; g++) {
                    float ss = 0.f;
                    #pragma unroll
                    for (int q = 0; q < 4; q++) {
                        float a0 = acc[mt][g*4+q][rr*2+0];
                        float a1 = acc[mt][g*4+q][rr*2+1];
                        ss += a0*a0 + a1*a1;
                    }
                    ss += __shfl_xor_sync(0xffffffffu, ss, 1);
                    ss += __shfl_xor_sync(0xffffffffu, ss, 2);
                    float inv = 1.f / fmaxf(sqrtf(ss), 1e-12f);
                    #pragma unroll
                    for (int q = 0; q < 4; q++) {
                        acc[mt][g*4+q][rr*2+0] *= inv;
                        acc[mt][g*4+q][rr*2+1] *= inv;
                    }
                }
    }

    // epilogue
    #pragma unroll
    for (int mt = 0; mt < 4; mt++) {
        #pragma unroll
        for (int rr = 0; rr < 2; rr++) {
            int mloc = oc0 + warpm0 + mt*16 + rr*8 + gid;
            float bi = bias ? bias[mloc] : 0.f;
            size_t ob = ((size_t)b*oc_out + oc_base + mloc)*SPA + p0 + warpn0 + tig*2;
            float psum = 0.f, psq = 0.f;
            #pragma unroll
            for (int nt = 0; nt < 8; nt++) {
                float2 v;
                v.x = acc[mt][nt][rr*2 + 0] + bi;
                v.y = acc[mt][nt][rr*2 + 1] + bi;
                if (res) {
                    float2 rv = *(const float2*)(res + ob + nt*8);
                    v.x += rv.x; v.y += rv.y;
                }
                if (flags & 4) { v.x = rtf(v.x); v.y = rtf(v.y); }
                *(float2*)(out + ob + nt*8) = v;
                if (flags & 2) { psum += v.x + v.y; psq += v.x*v.x + v.y*v.y; }
            }
            if (flags & 2) {
                psum += __shfl_xor_sync(0xffffffffu, psum, 1);
                psum += __shfl_xor_sync(0xffffffffu, psum, 2);
                psq  += __shfl_xor_sync(0xffffffffu, psq, 1);
                psq  += __shfl_xor_sync(0xffffffffu, psq, 2);
                if (tig == 0) {
                    atomicAdd(&s1g[b*oc_out + mloc], psum);
                    atomicAdd(&s2g[b*oc_out + mloc], psq);
                }
            }
        }
    }
}

// ------------------------- q_probe[bh][w] = sum_{dh,hh} qn -------------------
__global__ void probe_kernel(const float* __restrict__ qkv, float* __restrict__ probe) {
    int bh = blockIdx.x;
    int b = bh >> 3, head = bh & 7;
    int tid = threadIdx.x;
    int w = tid & 31, grp = tid >> 5;
    const float* qb = qkv + ((size_t)b*768 + head*32)*SPA;
    float s = 0.f;
    for (int idx = grp; idx < 32*256; idx += 8)
        s += qb[(size_t)idx*32 + w];
    __shared__ float red[8][32];
    red[grp][w] = s;
    __syncthreads();
    if (tid < 32) {
        float t = 0.f;
        #pragma unroll
        for (int g = 0; g < 8; g++) t += red[g][tid];
        probe[bh*32 + tid] = t;
    }
}

// ------------------------- top-k selection + gather -------------------------
__global__ void select_kernel(const float* __restrict__ qkv,
                              const float* __restrict__ probe,
                              float* __restrict__ k2, float* __restrict__ v2) {
    int bh = blockIdx.x;
    int b = bh >> 3, head = bh & 7;
    int tid = threadIdx.x;
    int w = tid & 31;
    const float* kb = qkv + ((size_t)b*768 + 256 + head*32)*SPA;
    const float* vb = qkv + ((size_t)b*768 + 512 + head*32)*SPA;
    __shared__ float pr[32];
    __shared__ float kh[32][32];
    __shared__ float sh[32];
    __shared__ int   sel_dh[8];
    __shared__ float ks2[256][33];
    __shared__ float sw[256];
    __shared__ int   sel_hh[8];
    if (tid < 32) pr[tid] = probe[bh*32 + tid];
    for (int dh = tid >> 5; dh < 32; dh += 8) {
        float s = 0.f;
        for (int hh = 0; hh < 256; hh++)
            s += kb[(size_t)dh*8192 + hh*32 + w];
        kh[dh][w] = s;
    }
    __syncthreads();
    if (tid < 32) {
        float s = 0.f;
        #pragma unroll
        for (int w2 = 0; w2 < 32; w2++) s += pr[w2] * kh[tid][w2];
        sh[tid] = s;
    }
    __syncthreads();
    if (tid == 0) {
        unsigned used = 0u;
        for (int j = 0; j < 8; j++) {
            int best = -1; float bv = -FLT_MAX;
            for (int d2 = 0; d2 < 32; d2++) {
                if ((used >> d2) & 1u) continue;
                if (best < 0 || sh[d2] > bv) { best = d2; bv = sh[d2]; }
            }
            used |= 1u << best;
            sel_dh[j] = best;
        }
    }
    __syncthreads();
    for (int hh = tid >> 5; hh < 256; hh += 8) {
        float s = 0.f;
        #pragma unroll
        for (int j = 0; j < 8; j++)
            s += kb[(size_t)sel_dh[j]*8192 + hh*32 + w];
        ks2[hh][w] = s;
    }
    __syncthreads();
    {
        float s = 0.f;
        #pragma unroll
        for (int w2 = 0; w2 < 32; w2++) s += pr[w2] * ks2[tid][w2];
        sw[tid] = s;
    }
    __syncthreads();
    if (tid == 0) {
        unsigned um[8] = {0,0,0,0,0,0,0,0};
        for (int j = 0; j < 8; j++) {
            int best = -1; float bv = -FLT_MAX;
            for (int h2 = 0; h2 < 256; h2++) {
                if ((um[h2 >> 5] >> (h2 & 31)) & 1u) continue;
                if (best < 0 || sw[h2] > bv) { best = h2; bv = sw[h2]; }
            }
            um[best >> 5] |= 1u << (best & 31);
            sel_hh[j] = best;
        }
    }
    __syncthreads();
    for (int j = tid >> 5; j < 64; j += 8) {
        int jd = j >> 3, jw = j & 7;
        size_t src = (size_t)sel_dh[jd]*8192 + sel_hh[jw]*32 + w;
        k2[(size_t)(bh*64 + j)*32 + w] = kb[src];
        v2[(size_t)(bh*64 + j)*32 + w] = vb[src];
    }
}

// ------------------------- attention (64 keys) + transpose write ------------
__global__ void attn_kernel(const float* __restrict__ qkv,
                            const float* __restrict__ k2,
                            const float* __restrict__ v2,
                            float* __restrict__ o_r) {
    __shared__ float k2s[64*33];
    __shared__ float v2s[64*33];
    __shared__ float os[32*129];
    int bh = blockIdx.y;
    int b = bh >> 3, head = bh & 7;
    int i0 = blockIdx.x * 128;
    int tid = threadIdx.x;
    int lane = tid & 31, wid = tid >> 5;
    #pragma unroll
    for (int r = 0; r < 8; r++) {
        int jj = wid + r*8;
        k2s[jj*33 + lane] = k2[(size_t)(bh*64 + jj)*32 + lane];
        v2s[jj*33 + lane] = v2[(size_t)(bh*64 + jj)*32 + lane];
    }
    __syncthreads();
    const float* qb = qkv + ((size_t)b*768 + head*32)*SPA;
    for (int it = 0; it < 16; it++) {
        int li = wid*16 + it;
        int i = i0 + li;
        float qv = qb[(size_t)i*32 + lane];
        float s0 = 0.f, s1 = 0.f;
        #pragma unroll
        for (int d = 0; d < 32; d++) {
            float qd = __shfl_sync(0xffffffffu, qv, d);
            s0 = fmaf(qd, k2s[lane*33 + d], s0);
            s1 = fmaf(qd, k2s[(lane+32)*33 + d], s1);
        }
        float mx = fmaxf(s0, s1);
        #pragma unroll
        for (int o = 16; o; o >>= 1) mx = fmaxf(mx, __shfl_xor_sync(0xffffffffu, mx, o));
        float p0 = expf(s0 - mx), p1 = expf(s1 - mx);
        float ssm = p0 + p1;
        #pragma unroll
        for (int o = 16; o; o >>= 1) ssm += __shfl_xor_sync(0xffffffffu, ssm, o);
        float inv = 1.f / ssm;
        float ov = 0.f;
        #pragma unroll
        for (int j = 0; j < 32; j++) {
            float pa = __shfl_sync(0xffffffffu, p0, j);
            float pb = __shfl_sync(0xffffffffu, p1, j);
            ov = fmaf(pa, v2s[j*33 + lane], ov);
            ov = fmaf(pb, v2s[(j+32)*33 + lane], ov);
        }
        os[lane*129 + li] = ov * inv;
    }
    __syncthreads();
    #pragma unroll
    for (int dblk = 0; dblk < 4; dblk++) {
        int d = dblk*8 + wid;
        float* ob = o_r + ((size_t)b*256 + head*32 + d)*SPA + i0;
        #pragma unroll
        for (int cs = 0; cs < 4; cs++)
            ob[cs*32 + lane] = rtf(os[d*129 + cs*32 + lane]);   // pre-round for GEMM
    }
}

// ------------------------- depthwise 3x3 (SAME), conv branch ----------------
__global__ void dwconv3_kernel(const float* __restrict__ in, const float* __restrict__ w,
                               const float* __restrict__ bias, float* __restrict__ out) {
    int b = blockIdx.z;
    int c = blockIdx.y;
    int C = gridDim.y;
    int hh = blockIdx.x*8 + (threadIdx.x >> 5);
    int ww = threadIdx.x & 31;
    const float* ib = in + ((size_t)b*C + c)*SPA;
    float s = bias[c];
    #pragma unroll
    for (int dy = 0; dy < 3; dy++) {
        int y = hh + dy - 1;
        if (y < 0 || y >= HDIM) continue;
        #pragma unroll
        for (int dx = 0; dx < 3; dx++) {
            int x2 = ww + dx - 1;
            if (x2 < 0 || x2 >= WDIM) continue;
            s = fmaf(ib[y*WDIM + x2], w[c*9 + dy*3 + dx], s);
        }
    }
    out[((size_t)b*C + c)*SPA + hh*WDIM + ww] = rtf(s);   // pre-round for GEMM
}

// ---------- depthwise 3x3 over gelu(inorm(raw)) using precomputed stats -----
__global__ void dwconv3_gn_kernel(const float* __restrict__ in, const float* __restrict__ w,
                                  const float* __restrict__ bias,
                                  const float* __restrict__ s1, const float* __restrict__ s2,
                                  float* __restrict__ out) {
    __shared__ float tile[10*32];
    int b = blockIdx.z, c = blockIdx.y;
    int C = gridDim.y;
    int bc = b*C + c;
    float m  = s1[bc] * (1.f/8192.f);
    float var = s2[bc] * (1.f/8192.f) - m*m;
    float r = rsqrtf(var + 1e-5f);
    int hh0 = blockIdx.x * 8;
    const float* ib = in + (size_t)bc*SPA;
    for (int i = threadIdx.x; i < 320; i += 256) {
        int row = i >> 5, col = i & 31;
        int y = hh0 + row - 1;
        float v = 0.f;
        if (y >= 0 && y < HDIM) {
            float t = (ib[y*32 + col] - m) * r;
            v = 0.5f * t * (1.f + erff(t * 0.70710678118654752f));
        }
        tile[i] = v;
    }
    __syncthreads();
    int hl = threadIdx.x >> 5, ww = threadIdx.x & 31;
    float s = bias[c];
    #pragma unroll
    for (int dy = 0; dy < 3; dy++) {
        #pragma unroll
        for (int dx = 0; dx < 3; dx++) {
            int x2 = ww + dx - 1;
            if (x2 < 0 || x2 >= WDIM) continue;
            s = fmaf(tile[(hl + dy)*32 + x2], w[c*9 + dy*3 + dx], s);
        }
    }
    out[(size_t)bc*SPA + (hh0 + hl)*32 + ww] = s;
}

// ------------------------- instance norm (plain, final output) --------------
__global__ void inorm_kernel(const float* __restrict__ in, float* __restrict__ out) {
    size_t base = (size_t)blockIdx.x * SPA;
    int tid = threadIdx.x;
    float v[32];
    double s = 0.0, s2 = 0.0;
    #pragma unroll
    for (int j = 0; j < 32; j++) {
        float t = in[base + j*256 + tid];
        v[j] = t;
        s += t; s2 += (double)t*(double)t;
    }
    __shared__ double rs[8], rq[8];
    __shared__ float mv[2];
    #pragma unroll
    for (int o = 16; o; o >>= 1) {
        s  += __shfl_xor_sync(0xffffffffu, s, o);
        s2 += __shfl_xor_sync(0xffffffffu, s2, o);
    }
    if ((tid & 31) == 0) { rs[tid >> 5] = s; rq[tid >> 5] = s2; }
    __syncthreads();
    if (tid == 0) {
        double ts = 0.0, tq = 0.0;
        #pragma unroll
        for (int g = 0; g < 8; g++) { ts += rs[g]; tq += rq[g]; }
        double m   = ts / (double)SPA;
        double var = tq / (double)SPA - m*m;
        mv[0] = (float)m;
        mv[1] = (float)(1.0 / sqrt(var + 1e-5));
    }
    __syncthreads();
    float m = mv[0], r = mv[1];
    #pragma unroll
    for (int j = 0; j < 32; j++)
        out[base + j*256 + tid] = (v[j] - m) * r;
}

// --------- h2 = gelu(norm_ffraw(add)) + gelu(inorm(in)) ; add = raw ff1 -----
__global__ void inorm_addgn_kernel(const float* __restrict__ in,
                                   const float* __restrict__ addraw,
                                   const float* __restrict__ s1,
                                   const float* __restrict__ s2,
                                   float* __restrict__ out) {
    size_t base = (size_t)blockIdx.x * SPA;
    int tid = threadIdx.x;
    float ma  = s1[blockIdx.x] * (1.f/8192.f);
    float va  = s2[blockIdx.x] * (1.f/8192.f) - ma*ma;
    float ra  = rsqrtf(va + 1e-5f);
    float v[32];
    double s = 0.0, s2l = 0.0;
    #pragma unroll
    for (int j = 0; j < 32; j++) {
        float t = in[base + j*256 + tid];
        v[j] = t;
        s += t; s2l += (double)t*(double)t;
    }
    __shared__ double rs[8], rq[8];
    __shared__ float mv[2];
    #pragma unroll
    for (int o = 16; o; o >>= 1) {
        s   += __shfl_xor_sync(0xffffffffu, s, o);
        s2l += __shfl_xor_sync(0xffffffffu, s2l, o);
    }
    if ((tid & 31) == 0) { rs[tid >> 5] = s; rq[tid >> 5] = s2l; }
    __syncthreads();
    if (tid == 0) {
        double ts = 0.0, tq = 0.0;
        #pragma unroll
        for (int g = 0; g < 8; g++) { ts += rs[g]; tq += rq[g]; }
        double m   = ts / (double)SPA;
        double var = tq / (double)SPA - m*m;
        mv[0] = (float)m;
        mv[1] = (float)(1.0 / sqrt(var + 1e-5));
    }
    __syncthreads();
    float m = mv[0], r = mv[1];
    #pragma unroll
    for (int j = 0; j < 32; j++) {
        float t = (v[j] - m) * r;
        t = 0.5f * t * (1.f + erff(t * 0.70710678118654752f));
        float a = (addraw[base + j*256 + tid] - ma) * ra;
        a = 0.5f * a * (1.f + erff(a * 0.70710678118654752f));
        out[base + j*256 + tid] = rtf(t + a);   // pre-round for ff2 GEMM
    }
}

// ------------------------- host orchestration -------------------------------
extern "C" void kernel_launch(void* const* d_in, const int* in_sizes, int n_in,
                              void* d_out, int out_size) {
    (void)in_sizes; (void)n_in; (void)out_size;
    const float* x      = (const float*)d_in[0];
    const float* cln_g  = (const float*)d_in[1];
    const float* cln_b  = (const float*)d_in[2];
    const float* w_qkv  = (const float*)d_in[3];
    const float* w_out  = (const float*)d_in[4];
    const float* b_out  = (const float*)d_in[5];
    const float* w_dw   = (const float*)d_in[6];
    const float* b_dw   = (const float*)d_in[7];
    const float* w_comb = (const float*)d_in[8];
    const float* b_comb = (const float*)d_in[9];
    const float* w_ff1  = (const float*)d_in[10];
    const float* b_ff1  = (const float*)d_in[11];
    const float* w_ffdw = (const float*)d_in[12];
    const float* b_ffdw = (const float*)d_in[13];
    const float* w_ff2  = (const float*)d_in[14];
    const float* b_ff2  = (const float*)d_in[15];
    float* out = (float*)d_out;

    float *p_xn, *p_xs, *p_qkv, *p_or, *p_attn, *p_conv, *p_comb, *p_ff1, *p_ffdw, *p_ff2;
    float *p_probe, *p_k2, *p_v2, *p_wt, *p_s1, *p_s2;
    cudaGetSymbolAddress((void**)&p_xn,   g_xn);
    cudaGetSymbolAddress((void**)&p_xs,   g_xs);
    cudaGetSymbolAddress((void**)&p_qkv,  g_qkv);
    cudaGetSymbolAddress((void**)&p_or,   g_or);
    cudaGetSymbolAddress((void**)&p_attn, g_attn);
    cudaGetSymbolAddress((void**)&p_conv, g_conv);
    cudaGetSymbolAddress((void**)&p_comb, g_comb);
    cudaGetSymbolAddress((void**)&p_ff1,  g_ff1);
    cudaGetSymbolAddress((void**)&p_ffdw, g_ffdw);
    cudaGetSymbolAddress((void**)&p_ff2,  g_ff2);
    cudaGetSymbolAddress((void**)&p_probe,g_probe);
    cudaGetSymbolAddress((void**)&p_k2,   g_k2);
    cudaGetSymbolAddress((void**)&p_v2,   g_v2);
    cudaGetSymbolAddress((void**)&p_wt,   g_wt);
    cudaGetSymbolAddress((void**)&p_s1,   g_s1);
    cudaGetSymbolAddress((void**)&p_s2,   g_s2);

    static bool attr_set = false;
    if (!attr_set) {
        cudaFuncSetAttribute(gemm_tf32,
            cudaFuncAttributeMaxDynamicSharedMemorySize, 65536);
        attr_set = true;
    }
    const int GSM = 65536;

    // Launches 1..5 (so launch #6 = qk GEMM lands in the ncu -s 5 -c 1 window)
    transpose_split_qk<<<dim3(8, 16), 256>>>(w_qkv, p_wt + WT_QK);               // 1
    chan_ln_kernel<<<dim3(HDIM, BATCH), 256>>>(x, cln_g, cln_b, p_xn, p_xs);     // 2
    transpose_kernel<<<dim3(8, 8), 256>>>(w_qkv + 512*256, p_wt + WT_V, 256, 256); // 3
    transpose4_kernel<<<704, 256>>>(w_out, w_comb, w_ff1, w_ff2, p_wt);          // 4
    zero_stats<<<32, 256>>>(p_s1, p_s2);                                         // 5

    // 6) q,k = exact tf32 split GEMM (K=768) + fused l2norm   [PROFILED]
    gemm_tf32<<<dim3(4, 64, 8), 128, GSM>>>(p_xn, p_xs, 512, 256, 768, 1,
        p_wt + WT_QK, 512, nullptr, nullptr, p_qkv, 768, 0, /*flags=*/1, nullptr, nullptr);
    // 7) v = single tf32 GEMM (K=256)
    gemm_tf32<<<dim3(2, 64, 8), 128, GSM>>>(p_xn, nullptr, 256, 256, 256, 0,
        p_wt + WT_V, 256, nullptr, nullptr, p_qkv, 768, 512, 0, nullptr, nullptr);
    // 8) q_probe
    probe_kernel<<<NBH, 256>>>(p_qkv, p_probe);
    // 9) top-k selection + gather
    select_kernel<<<NBH, 256>>>(p_qkv, p_probe, p_k2, p_v2);
    // 10) attention + transpose (output pre-rounded)
    attn_kernel<<<dim3(64, NBH), 256>>>(p_qkv, p_k2, p_v2, p_or);
    // 11) attn_branch = conv1x1(o_r, w_out, b_out)  (output pre-rounded)
    gemm_tf32<<<dim3(2, 64, 8), 128, GSM>>>(p_or, nullptr, 256, 256, 256, 0,
        p_wt + WT_OUT, 256, b_out, nullptr, p_attn, 256, 0, /*flags=*/4, nullptr, nullptr);
    // 12) conv_branch = dwconv3(x)  (output pre-rounded)
    dwconv3_kernel<<<dim3(32, 256, 8), 256>>>(x, w_dw, b_dw, p_conv);
    // 13) comb = conv1x1(concat(attn, conv)) + x  (output pre-rounded)
    gemm_tf32<<<dim3(2, 64, 8), 128, GSM>>>(p_attn, p_conv, 256, 256, 512, 0,
        p_wt + WT_COMB, 256, b_comb, x, p_comb, 256, 0, /*flags=*/4, nullptr, nullptr);
    // 14) ff1 raw (+ fused per-(b,c) stats)
    gemm_tf32<<<dim3(8, 64, 8), 128, GSM>>>(p_comb, nullptr, 256, 256, 256, 0,
        p_wt + WT_FF1, 1024, b_ff1, nullptr, p_ff1, 1024, 0, /*flags=*/2, p_s1, p_s2);
    // 15) ffdw = dwconv3(gelu(inorm(ff1)))
    dwconv3_gn_kernel<<<dim3(32, 1024, 8), 256>>>(p_ff1, w_ffdw, b_ffdw, p_s1, p_s2, p_ffdw);
    // 16) h2 = gelu(inorm_ff1(ff1)) + gelu(inorm(ffdw))  (output pre-rounded)
    inorm_addgn_kernel<<<BATCH*FFI, 256>>>(p_ffdw, p_ff1, p_s1, p_s2, p_ffdw);
    // 17) ff2
    gemm_tf32<<<dim3(2, 64, 8), 128, GSM>>>(p_ffdw, nullptr, 1024, 1024, 1024, 0,
        p_wt + WT_FF2, 256, b_ff2, nullptr, p_ff2, 256, 0, 0, nullptr, nullptr);
    // 18) out = inorm(ff2)
    inorm_kernel<<<BATCH*CDIM, 256>>>(p_ff2, out);
}